// round 8
// baseline (speedup 1.0000x reference)
#include <cuda_runtime.h>
#include <cuda_bf16.h>
#include <cstdint>

typedef uint32_t u32;

#define S_LEN 2048
#define NH 16
#define DIM 64
#define BLKM 64          // T rows per CTA
#define BLKS 128         // K/V rows per tile
#define NMB 32           // S_LEN / BLKM
#define ROWSTRIDE 3072   // 3*NH*DIM floats between consecutive s rows

#define HLQ 8192         // one [64][64] bf16 half-tile
#define HLK 16384        // one [128][64] bf16 half-tile
#define SLOT (2*HLK)     // ring slot: hi+lo split tile, 32KB
#define RING 3

#define OFF_Q    0                   // 2Q split (16KB)
#define OFF_O2   16384               // -O2 split (16KB)
#define OFF_RED  32768               // f32 reduce staging (16KB)
#define OFF_RING 49152               // 3 x 32KB ring
#define SMEM_TOTAL (OFF_RING + RING*SLOT)   // 147456 B

#define NCONS 128
#define NTHREADS 192

#define BAR_SYNC(id, cnt)   asm volatile("bar.sync %0, %1;"   :: "r"(id), "r"(cnt) : "memory")
#define BAR_ARRIVE(id, cnt) asm volatile("bar.arrive %0, %1;" :: "r"(id), "r"(cnt) : "memory")
#define CBAR() BAR_SYNC(7, NCONS)    // consumers-only barrier

// ------------------------------------------------------------------ helpers
__device__ __forceinline__ u32 smem_u32(const void* p) {
    u32 a; asm("{ .reg .u64 t; cvta.to.shared.u64 t, %1; cvt.u32.u64 %0, t; }"
               : "=r"(a) : "l"(p));
    return a;
}
__device__ __forceinline__ u32 off64(int r, int cb) { return (u32)(r * 128 + (cb ^ ((r & 7) << 4))); }

__device__ __forceinline__ void ldsm4(u32 a, u32& r0, u32& r1, u32& r2, u32& r3) {
    asm volatile("ldmatrix.sync.aligned.m8n8.x4.shared.b16 {%0,%1,%2,%3}, [%4];"
        : "=r"(r0), "=r"(r1), "=r"(r2), "=r"(r3) : "r"(a));
}
__device__ __forceinline__ void ldsm4t(u32 a, u32& r0, u32& r1, u32& r2, u32& r3) {
    asm volatile("ldmatrix.sync.aligned.m8n8.x4.trans.shared.b16 {%0,%1,%2,%3}, [%4];"
        : "=r"(r0), "=r"(r1), "=r"(r2), "=r"(r3) : "r"(a));
}
__device__ __forceinline__ void mma_bf16(float* c, u32 a0, u32 a1, u32 a2, u32 a3,
                                         u32 b0, u32 b1) {
    asm volatile("mma.sync.aligned.m16n8k16.row.col.f32.bf16.bf16.f32 "
        "{%0,%1,%2,%3}, {%4,%5,%6,%7}, {%8,%9}, {%0,%1,%2,%3};"
        : "+f"(c[0]), "+f"(c[1]), "+f"(c[2]), "+f"(c[3])
        : "r"(a0), "r"(a1), "r"(a2), "r"(a3), "r"(b0), "r"(b1));
}
// fast truncation split: hi = top16 (PRMT pack), lo = x - hi (rn bf16x2 pack)
__device__ __forceinline__ void split_pack(float v0, float v1, u32& hp, u32& lp) {
    u32 u0 = __float_as_uint(v0), u1 = __float_as_uint(v1);
    asm("prmt.b32 %0, %1, %2, 0x7632;" : "=r"(hp) : "r"(u0), "r"(u1));
    float lo0 = v0 - __uint_as_float(u0 & 0xFFFF0000u);
    float lo1 = v1 - __uint_as_float(u1 & 0xFFFF0000u);
    asm("cvt.rn.satfinite.bf16x2.f32 %0, %1, %2;" : "=r"(lp) : "f"(lo1), "f"(lo0));
}

// ---- producer: 128x64 fp32 gmem tile -> split-bf16 ring slot (64 threads) ----
__device__ __forceinline__ void prod_tile(char* sm, int base, const float* src, int ptid) {
#pragma unroll
    for (int g = 0; g < 4; ++g) {
        float4 v[8];
#pragma unroll
        for (int i = 0; i < 8; ++i) {
            int f = ptid + (g * 8 + i) * 64;
            int s = f >> 4, dq = (f & 15) << 2;
            v[i] = *reinterpret_cast<const float4*>(src + (size_t)s * ROWSTRIDE + dq);
        }
#pragma unroll
        for (int i = 0; i < 8; ++i) {
            int f = ptid + (g * 8 + i) * 64;
            int s = f >> 4, dq = (f & 15) << 2;
            u32 hp0, lp0, hp1, lp1;
            split_pack(v[i].x, v[i].y, hp0, lp0);
            split_pack(v[i].z, v[i].w, hp1, lp1);
            u32 o = off64(s, dq << 1);
            *reinterpret_cast<u32*>(sm + base + o)           = hp0;
            *reinterpret_cast<u32*>(sm + base + o + 4)       = hp1;
            *reinterpret_cast<u32*>(sm + base + HLK + o)     = lp0;
            *reinterpret_cast<u32*>(sm + base + HLK + o + 4) = lp1;
        }
    }
}

// ---- consumer Q load: 64x64 fp32 -> 2Q split tiles (128 threads) ----
__device__ __forceinline__ void load_q(char* sm, const float* src, int tid) {
#pragma unroll
    for (int it = 0; it < 8; ++it) {
        int f = tid + it * 128;
        int s = f >> 4, dq = (f & 15) << 2;
        float4 v = *reinterpret_cast<const float4*>(src + (size_t)s * ROWSTRIDE + dq);
        u32 hp0, lp0, hp1, lp1;
        split_pack(v.x * 2.0f, v.y * 2.0f, hp0, lp0);
        split_pack(v.z * 2.0f, v.w * 2.0f, hp1, lp1);
        u32 o = off64(s, dq << 1);
        *reinterpret_cast<u32*>(sm + OFF_Q + o)           = hp0;
        *reinterpret_cast<u32*>(sm + OFF_Q + o + 4)       = hp1;
        *reinterpret_cast<u32*>(sm + OFF_Q + HLQ + o)     = lp0;
        *reinterpret_cast<u32*>(sm + OFF_Q + HLQ + o + 4) = lp1;
    }
}

// ---- GEMM1: acc[32x64 slice] += A[rows x 64] * (B[128x64])^T, 3-term split ----
template <int HLA>
__device__ __forceinline__ void gemm_nT(u32 aHi, u32 bHi, float (&acc)[2][8][4],
                                        int lane, int mbase, int nbase) {
    const int arL = lane & 15, acL = (lane >> 4) << 4;
    const int brL = ((lane >> 4) << 3) + (lane & 7), bcL = ((lane >> 3) & 1) << 4;
#pragma unroll
    for (int kk = 0; kk < 4; ++kk) {
        const int kb = kk << 5;
        u32 aH[2][4], aL[2][4];
#pragma unroll
        for (int mt = 0; mt < 2; ++mt) {
            u32 ad = aHi + off64(mbase + mt * 16 + arL, kb + acL);
            ldsm4(ad,       aH[mt][0], aH[mt][1], aH[mt][2], aH[mt][3]);
            ldsm4(ad + HLA, aL[mt][0], aL[mt][1], aL[mt][2], aL[mt][3]);
        }
#pragma unroll
        for (int nt2 = 0; nt2 < 4; ++nt2) {
            u32 bd = bHi + off64(nbase + nt2 * 16 + brL, kb + bcL);
            u32 bh0, bh1, bh2, bh3, bl0, bl1, bl2, bl3;
            ldsm4(bd,       bh0, bh1, bh2, bh3);
            ldsm4(bd + HLK, bl0, bl1, bl2, bl3);
#pragma unroll
            for (int mt = 0; mt < 2; ++mt) {
                float* c0 = acc[mt][nt2 * 2];
                float* c1 = acc[mt][nt2 * 2 + 1];
                mma_bf16(c0, aH[mt][0], aH[mt][1], aH[mt][2], aH[mt][3], bh0, bh1);
                mma_bf16(c1, aH[mt][0], aH[mt][1], aH[mt][2], aH[mt][3], bh2, bh3);
                mma_bf16(c0, aH[mt][0], aH[mt][1], aH[mt][2], aH[mt][3], bl0, bl1);
                mma_bf16(c1, aH[mt][0], aH[mt][1], aH[mt][2], aH[mt][3], bl2, bl3);
                mma_bf16(c0, aL[mt][0], aL[mt][1], aL[mt][2], aL[mt][3], bh0, bh1);
                mma_bf16(c1, aL[mt][0], aL[mt][1], aL[mt][2], aL[mt][3], bh2, bh3);
            }
        }
    }
}

// ---- mask (absolute row/col) + in-register split into A-operand packs ----
__device__ __forceinline__ void mask_pack(float (&acc)[2][8][4],
                                          u32 (&pH)[2][4][4], u32 (&pL)[2][4][4],
                                          int lane, int rowAbs0, int colAbs0, bool diag) {
    if (diag) {
#pragma unroll
        for (int mt = 0; mt < 2; ++mt)
#pragma unroll
            for (int nt = 0; nt < 8; ++nt) {
                int col = colAbs0 + nt * 8 + ((lane & 3) << 1);
#pragma unroll
                for (int rr = 0; rr < 2; ++rr) {
                    int row = rowAbs0 + mt * 16 + (lane >> 2) + rr * 8;
                    if (col     > row) acc[mt][nt][rr * 2 + 0] = 0.0f;
                    if (col + 1 > row) acc[mt][nt][rr * 2 + 1] = 0.0f;
                }
            }
    }
#pragma unroll
    for (int mt = 0; mt < 2; ++mt)
#pragma unroll
        for (int kk = 0; kk < 4; ++kk) {
            split_pack(acc[mt][2*kk  ][0], acc[mt][2*kk  ][1], pH[mt][kk][0], pL[mt][kk][0]);
            split_pack(acc[mt][2*kk  ][2], acc[mt][2*kk  ][3], pH[mt][kk][1], pL[mt][kk][1]);
            split_pack(acc[mt][2*kk+1][0], acc[mt][2*kk+1][1], pH[mt][kk][2], pL[mt][kk][2]);
            split_pack(acc[mt][2*kk+1][2], acc[mt][2*kk+1][3], pH[mt][kk][3], pL[mt][kk][3]);
        }
}

// ---- GEMM2: po[32x64] += S_slice(regs) * B[k-slice x 64], B via ldmatrix.trans ----
__device__ __forceinline__ void gemm2_reg(const u32 (&pH)[2][4][4], const u32 (&pL)[2][4][4],
                                          u32 bHi, float (&po)[2][8][4],
                                          int lane, int kbase) {
    const int brL = (((lane >> 3) & 1) << 3) + (lane & 7), bcL = (lane >> 4) << 4;
#pragma unroll
    for (int kk = 0; kk < 4; ++kk) {
#pragma unroll
        for (int nt2 = 0; nt2 < 4; ++nt2) {
            u32 bd = bHi + off64(kbase + kk * 16 + brL, (nt2 << 5) + bcL);
            u32 bh0, bh1, bh2, bh3, bl0, bl1, bl2, bl3;
            ldsm4t(bd,       bh0, bh1, bh2, bh3);
            ldsm4t(bd + HLK, bl0, bl1, bl2, bl3);
#pragma unroll
            for (int mt = 0; mt < 2; ++mt) {
                float* c0 = po[mt][nt2 * 2];
                float* c1 = po[mt][nt2 * 2 + 1];
                mma_bf16(c0, pH[mt][kk][0], pH[mt][kk][1], pH[mt][kk][2], pH[mt][kk][3], bh0, bh1);
                mma_bf16(c1, pH[mt][kk][0], pH[mt][kk][1], pH[mt][kk][2], pH[mt][kk][3], bh2, bh3);
                mma_bf16(c0, pH[mt][kk][0], pH[mt][kk][1], pH[mt][kk][2], pH[mt][kk][3], bl0, bl1);
                mma_bf16(c1, pH[mt][kk][0], pH[mt][kk][1], pH[mt][kk][2], pH[mt][kk][3], bl2, bl3);
                mma_bf16(c0, pL[mt][kk][0], pL[mt][kk][1], pL[mt][kk][2], pL[mt][kk][3], bh0, bh1);
                mma_bf16(c1, pL[mt][kk][0], pL[mt][kk][1], pL[mt][kk][2], pL[mt][kk][3], bh2, bh3);
            }
        }
    }
}

#define ZERO_PO(po) \
    _Pragma("unroll") for (int mt = 0; mt < 2; ++mt) \
    _Pragma("unroll") for (int nt = 0; nt < 8; ++nt) \
    _Pragma("unroll") for (int e = 0; e < 4; ++e) (po)[mt][nt][e] = 0.0f;

__global__ void __launch_bounds__(NTHREADS, 1)
ttt_mma_kernel(const float* __restrict__ qkv, float* __restrict__ out) {
    extern __shared__ char sm[];
    const u32 sb = smem_u32(sm);
    const int tid = threadIdx.x;

    const int mb = (NMB - 1) - (int)blockIdx.y;     // heavy T-blocks first
    const int bh = blockIdx.x, b = bh >> 4, h = bh & 15;
    const float* base = qkv + (size_t)b * S_LEN * ROWSTRIDE + h * DIM;
    const float* gQ = base;
    const float* gK = base + NH * DIM;
    const float* gV = base + 2 * NH * DIM;
    const int t0 = mb * BLKM;
    const int nK = (mb >> 1) + 1;                   // 128-row K blocks needed
    const bool evenMb = (mb & 1) == 0;

    // =========================== producer warps (wid 4-5) ===========================
    if (tid >= NCONS) {
        const int ptid = tid - NCONS;
        int slot = 0;
        const int totalT = 3 * nK;   // pass1: K_0..K_{nK-1}; pass2: K_0,V_0,...,K,V
        for (int t = 0; t < totalT; ++t) {
            if (t >= RING) BAR_SYNC(4 + slot, NTHREADS);     // wait slot empty
            const float* src;
            if (t < nK) {
                src = gK + (size_t)t * BLKS * ROWSTRIDE;
            } else {
                int u = t - nK, j = u >> 1;
                src = ((u & 1) ? gV : gK) + (size_t)j * BLKS * ROWSTRIDE;
            }
            prod_tile(sm, OFF_RING + slot * SLOT, src, ptid);
            asm volatile("fence.acq_rel.cta;" ::: "memory");
            BAR_ARRIVE(1 + slot, NTHREADS);                  // mark slot full
            slot = (slot == RING - 1) ? 0 : slot + 1;
        }
        return;
    }

    // =========================== consumer warps (wid 0-3) ===========================
    const int lane = tid & 31, wid = tid >> 5;
    const int wm = wid & 1, wn = wid >> 1;
    const int mbase = wm * 32, kbase = wn * 64;

    load_q(sm, gQ + (size_t)t0 * ROWSTRIDE, tid);   // 2Q
    CBAR();

    int slot = 0;
    // ================= pass 1: po = partial of tril(2Q K^T) K  (= 2*O2) =================
    float po[2][8][4];
    ZERO_PO(po);
    for (int j = 0; j < nK; ++j) {
        BAR_SYNC(1 + slot, NTHREADS);               // wait K_j full
        const u32 ringb = sb + OFF_RING + slot * SLOT;
        const bool active = !(j == nK - 1 && evenMb && wn == 1);  // dead diagonal half
        if (active) {
            float acc1[2][8][4];
            ZERO_PO(acc1);
            gemm_nT<HLQ>(sb + OFF_Q, ringb, acc1, lane, mbase, kbase);
            u32 pH[2][4][4], pL[2][4][4];
            mask_pack(acc1, pH, pL, lane, t0 + mbase, j * BLKS + kbase, j == nK - 1);
            gemm2_reg(pH, pL, ringb, po, lane, kbase);
        }
        BAR_ARRIVE(4 + slot, NTHREADS);             // release K_j
        slot = (slot == RING - 1) ? 0 : slot + 1;
    }

    // cross-warp reduce po (wn pairs) -> -O2 split tiles in sO2
    if (wn == 1) {
#pragma unroll
        for (int mt = 0; mt < 2; ++mt)
#pragma unroll
            for (int nt = 0; nt < 8; ++nt)
#pragma unroll
                for (int rr = 0; rr < 2; ++rr) {
                    int rl = mt * 16 + (lane >> 2) + rr * 8;
                    int col = nt * 8 + ((lane & 3) << 1);
                    float2 v = make_float2(po[mt][nt][rr * 2], po[mt][nt][rr * 2 + 1]);
                    *reinterpret_cast<float2*>(sm + OFF_RED + wm * 8192 + rl * 256 + col * 4) = v;
                }
    }
    CBAR();
    if (wn == 0) {
#pragma unroll
        for (int mt = 0; mt < 2; ++mt)
#pragma unroll
            for (int nt = 0; nt < 8; ++nt)
#pragma unroll
                for (int rr = 0; rr < 2; ++rr) {
                    int rl = mt * 16 + (lane >> 2) + rr * 8;
                    int col = nt * 8 + ((lane & 3) << 1);
                    float2 p = *reinterpret_cast<float2*>(sm + OFF_RED + wm * 8192 + rl * 256 + col * 4);
                    float v0 = -0.5f * (po[mt][nt][rr * 2]     + p.x);
                    float v1 = -0.5f * (po[mt][nt][rr * 2 + 1] + p.y);
                    u32 hp, lp;
                    split_pack(v0, v1, hp, lp);
                    u32 o = off64(mbase + rl, col << 1);
                    *reinterpret_cast<u32*>(sm + OFF_O2 + o)       = hp;
                    *reinterpret_cast<u32*>(sm + OFF_O2 + HLQ + o) = lp;
                }
    }
    CBAR();

    // ===== pass 2: po = partial of tril(2Q K^T + (-O2) K^T) V = (2A1 - A2) V =====
    ZERO_PO(po);
    for (int j = 0; j < nK; ++j) {
        BAR_SYNC(1 + slot, NTHREADS);               // wait K_j full
        const u32 ringK = sb + OFF_RING + slot * SLOT;
        const bool active = !(j == nK - 1 && evenMb && wn == 1);
        float acc1[2][8][4];
        if (active) {
            ZERO_PO(acc1);
            gemm_nT<HLQ>(sb + OFF_Q,  ringK, acc1, lane, mbase, kbase);  // 2Q K^T
            gemm_nT<HLQ>(sb + OFF_O2, ringK, acc1, lane, mbase, kbase);  // += (-O2) K^T
        }
        BAR_ARRIVE(4 + slot, NTHREADS);             // release K_j (acc1 is in regs)
        slot = (slot == RING - 1) ? 0 : slot + 1;

        u32 pH[2][4][4], pL[2][4][4];
        if (active)
            mask_pack(acc1, pH, pL, lane, t0 + mbase, j * BLKS + kbase, j == nK - 1);

        BAR_SYNC(1 + slot, NTHREADS);               // wait V_j full (prefilled under GEMM1)
        if (active)
            gemm2_reg(pH, pL, sb + OFF_RING + slot * SLOT, po, lane, kbase);  // += S V
        BAR_ARRIVE(4 + slot, NTHREADS);             // release V_j
        slot = (slot == RING - 1) ? 0 : slot + 1;
    }

    // cross-warp reduce po -> final out
    if (wn == 1) {
#pragma unroll
        for (int mt = 0; mt < 2; ++mt)
#pragma unroll
            for (int nt = 0; nt < 8; ++nt)
#pragma unroll
                for (int rr = 0; rr < 2; ++rr) {
                    int rl = mt * 16 + (lane >> 2) + rr * 8;
                    int col = nt * 8 + ((lane & 3) << 1);
                    float2 v = make_float2(po[mt][nt][rr * 2], po[mt][nt][rr * 2 + 1]);
                    *reinterpret_cast<float2*>(sm + OFF_RED + wm * 8192 + rl * 256 + col * 4) = v;
                }
    }
    CBAR();
    if (wn == 0) {
#pragma unroll
        for (int mt = 0; mt < 2; ++mt)
#pragma unroll
            for (int nt = 0; nt < 8; ++nt)
#pragma unroll
                for (int rr = 0; rr < 2; ++rr) {
                    int rl = mt * 16 + (lane >> 2) + rr * 8;
                    int col = nt * 8 + ((lane & 3) << 1);
                    float2 p = *reinterpret_cast<float2*>(sm + OFF_RED + wm * 8192 + rl * 256 + col * 4);
                    float2 v = make_float2(po[mt][nt][rr * 2] + p.x,
                                           po[mt][nt][rr * 2 + 1] + p.y);
                    size_t off = (((size_t)b * S_LEN + t0 + mbase + rl) * NH + h) * DIM + col;
                    *reinterpret_cast<float2*>(out + off) = v;
                }
    }
}

extern "C" void kernel_launch(void* const* d_in, const int* in_sizes, int n_in,
                              void* d_out, int out_size) {
    const float* qkv = (const float*)d_in[0];
    float* out = (float*)d_out;
    cudaFuncSetAttribute(ttt_mma_kernel, cudaFuncAttributeMaxDynamicSharedMemorySize,
                         SMEM_TOTAL);
    dim3 grid(32 /*b*h*/, NMB /*reversed T-blocks*/);
    ttt_mma_kernel<<<grid, NTHREADS, SMEM_TOTAL>>>(qkv, out);
}

// round 9
// speedup vs baseline: 2.0318x; 2.0318x over previous
#include <cuda_runtime.h>
#include <cuda_bf16.h>
#include <cstdint>

typedef uint32_t u32;

#define S_LEN 2048
#define NH 16
#define DIM 64
#define BLKM 64          // T rows per CTA
#define BLKS 64          // K/V rows per j-step
#define NMB 32           // S_LEN / BLKM
#define ROWSTRIDE 3072   // 3*NH*DIM floats between consecutive s rows

#define HL 8192          // one [64][64] bf16 half-tile (hi or lo)
// smem layout (each buffer = hi tile then lo tile, off64 swizzled)
#define OFF_Q   0
#define OFF_K   16384
#define OFF_V   32768
#define OFF_O2  49152
#define SMEM_TOTAL 65536               // -> 3 CTAs/SM
#define RED_OFF OFF_K                  // f32 staging for cross-warp reduce (16KB)

// ------------------------------------------------------------------ helpers
__device__ __forceinline__ u32 smem_u32(const void* p) {
    u32 a; asm("{ .reg .u64 t; cvta.to.shared.u64 t, %1; cvt.u32.u64 %0, t; }"
               : "=r"(a) : "l"(p));
    return a;
}
__device__ __forceinline__ u32 off64(int r, int cb) { return (u32)(r * 128 + (cb ^ ((r & 7) << 4))); }

__device__ __forceinline__ void ldsm4(u32 a, u32& r0, u32& r1, u32& r2, u32& r3) {
    asm volatile("ldmatrix.sync.aligned.m8n8.x4.shared.b16 {%0,%1,%2,%3}, [%4];"
        : "=r"(r0), "=r"(r1), "=r"(r2), "=r"(r3) : "r"(a));
}
__device__ __forceinline__ void ldsm4t(u32 a, u32& r0, u32& r1, u32& r2, u32& r3) {
    asm volatile("ldmatrix.sync.aligned.m8n8.x4.trans.shared.b16 {%0,%1,%2,%3}, [%4];"
        : "=r"(r0), "=r"(r1), "=r"(r2), "=r"(r3) : "r"(a));
}
__device__ __forceinline__ void mma_bf16(float* c, u32 a0, u32 a1, u32 a2, u32 a3,
                                         u32 b0, u32 b1) {
    asm volatile("mma.sync.aligned.m16n8k16.row.col.f32.bf16.bf16.f32 "
        "{%0,%1,%2,%3}, {%4,%5,%6,%7}, {%8,%9}, {%0,%1,%2,%3};"
        : "+f"(c[0]), "+f"(c[1]), "+f"(c[2]), "+f"(c[3])
        : "r"(a0), "r"(a1), "r"(a2), "r"(a3), "r"(b0), "r"(b1));
}
// fast truncation split: hi = top16 (PRMT pack), lo = x - hi (rn bf16x2 pack)
__device__ __forceinline__ void split_pack(float v0, float v1, u32& hp, u32& lp) {
    u32 u0 = __float_as_uint(v0), u1 = __float_as_uint(v1);
    asm("prmt.b32 %0, %1, %2, 0x7632;" : "=r"(hp) : "r"(u0), "r"(u1));
    float lo0 = v0 - __uint_as_float(u0 & 0xFFFF0000u);
    float lo1 = v1 - __uint_as_float(u1 & 0xFFFF0000u);
    asm("cvt.rn.satfinite.bf16x2.f32 %0, %1, %2;" : "=r"(lp) : "f"(lo1), "f"(lo0));
}

// ---- direct LDG load: 64 x 64 fp32 -> split-bf16 hi/lo swizzled smem (128 thr) ----
__device__ __forceinline__ void load_split(char* sm, int base, const float* src,
                                           float scale, int tid) {
#pragma unroll
    for (int it = 0; it < 8; ++it) {
        int f = tid + it * 128;
        int s = f >> 4, dq = (f & 15) << 2;
        float4 v = *reinterpret_cast<const float4*>(src + (size_t)s * ROWSTRIDE + dq);
        u32 hp0, lp0, hp1, lp1;
        split_pack(v.x * scale, v.y * scale, hp0, lp0);
        split_pack(v.z * scale, v.w * scale, hp1, lp1);
        u32 o = off64(s, dq << 1);
        *reinterpret_cast<u32*>(sm + base + o)          = hp0;
        *reinterpret_cast<u32*>(sm + base + o + 4)      = hp1;
        *reinterpret_cast<u32*>(sm + base + HL + o)     = lp0;
        *reinterpret_cast<u32*>(sm + base + HL + o + 4) = lp1;
    }
}

// ---- GEMM1: acc[32x32 slice] += A[64x64] * (B[64x64])^T, 3-term split ----
// This warp: A rows mbase..+31, B rows nbase..+31 (nbase = wn*32).
__device__ __forceinline__ void gemm_nT(u32 aHi, u32 bHi, float (&acc)[2][4][4],
                                        int lane, int mbase, int nbase) {
    const int arL = lane & 15, acL = (lane >> 4) << 4;
    const int brL = ((lane >> 4) << 3) + (lane & 7), bcL = ((lane >> 3) & 1) << 4;
#pragma unroll
    for (int kk = 0; kk < 4; ++kk) {
        const int kb = kk << 5;
        u32 aH[2][4], aL[2][4];
#pragma unroll
        for (int mt = 0; mt < 2; ++mt) {
            u32 ad = aHi + off64(mbase + mt * 16 + arL, kb + acL);
            ldsm4(ad,      aH[mt][0], aH[mt][1], aH[mt][2], aH[mt][3]);
            ldsm4(ad + HL, aL[mt][0], aL[mt][1], aL[mt][2], aL[mt][3]);
        }
#pragma unroll
        for (int nt2 = 0; nt2 < 2; ++nt2) {
            u32 bd = bHi + off64(nbase + nt2 * 16 + brL, kb + bcL);
            u32 bh0, bh1, bh2, bh3, bl0, bl1, bl2, bl3;
            ldsm4(bd,      bh0, bh1, bh2, bh3);
            ldsm4(bd + HL, bl0, bl1, bl2, bl3);
#pragma unroll
            for (int mt = 0; mt < 2; ++mt) {
                float* c0 = acc[mt][nt2 * 2];
                float* c1 = acc[mt][nt2 * 2 + 1];
                mma_bf16(c0, aH[mt][0], aH[mt][1], aH[mt][2], aH[mt][3], bh0, bh1);
                mma_bf16(c1, aH[mt][0], aH[mt][1], aH[mt][2], aH[mt][3], bh2, bh3);
                mma_bf16(c0, aH[mt][0], aH[mt][1], aH[mt][2], aH[mt][3], bl0, bl1);
                mma_bf16(c1, aH[mt][0], aH[mt][1], aH[mt][2], aH[mt][3], bl2, bl3);
                mma_bf16(c0, aL[mt][0], aL[mt][1], aL[mt][2], aL[mt][3], bh0, bh1);
                mma_bf16(c1, aL[mt][0], aL[mt][1], aL[mt][2], aL[mt][3], bh2, bh3);
            }
        }
    }
}

// ---- mask (absolute row/col) + in-register split into A-operand packs ----
__device__ __forceinline__ void mask_pack(float (&acc)[2][4][4],
                                          u32 (&pH)[2][2][4], u32 (&pL)[2][2][4],
                                          int lane, int rowAbs0, int colAbs0, bool diag) {
    if (diag) {
#pragma unroll
        for (int mt = 0; mt < 2; ++mt)
#pragma unroll
            for (int nt = 0; nt < 4; ++nt) {
                int col = colAbs0 + nt * 8 + ((lane & 3) << 1);
#pragma unroll
                for (int rr = 0; rr < 2; ++rr) {
                    int row = rowAbs0 + mt * 16 + (lane >> 2) + rr * 8;
                    if (col     > row) acc[mt][nt][rr * 2 + 0] = 0.0f;
                    if (col + 1 > row) acc[mt][nt][rr * 2 + 1] = 0.0f;
                }
            }
    }
#pragma unroll
    for (int mt = 0; mt < 2; ++mt)
#pragma unroll
        for (int kk = 0; kk < 2; ++kk) {
            split_pack(acc[mt][2*kk  ][0], acc[mt][2*kk  ][1], pH[mt][kk][0], pL[mt][kk][0]);
            split_pack(acc[mt][2*kk  ][2], acc[mt][2*kk  ][3], pH[mt][kk][1], pL[mt][kk][1]);
            split_pack(acc[mt][2*kk+1][0], acc[mt][2*kk+1][1], pH[mt][kk][2], pL[mt][kk][2]);
            split_pack(acc[mt][2*kk+1][2], acc[mt][2*kk+1][3], pH[mt][kk][3], pL[mt][kk][3]);
        }
}

// ---- GEMM2: po[32x64] += S_slice(regs, 32 k) * B[k-slice x 64], B via ldmatrix.trans ----
__device__ __forceinline__ void gemm2_reg(const u32 (&pH)[2][2][4], const u32 (&pL)[2][2][4],
                                          u32 bHi, float (&po)[2][8][4],
                                          int lane, int kbase) {
    const int brL = (((lane >> 3) & 1) << 3) + (lane & 7), bcL = (lane >> 4) << 4;
#pragma unroll
    for (int kk = 0; kk < 2; ++kk) {
#pragma unroll
        for (int nt2 = 0; nt2 < 4; ++nt2) {
            u32 bd = bHi + off64(kbase + kk * 16 + brL, (nt2 << 5) + bcL);
            u32 bh0, bh1, bh2, bh3, bl0, bl1, bl2, bl3;
            ldsm4t(bd,      bh0, bh1, bh2, bh3);
            ldsm4t(bd + HL, bl0, bl1, bl2, bl3);
#pragma unroll
            for (int mt = 0; mt < 2; ++mt) {
                float* c0 = po[mt][nt2 * 2];
                float* c1 = po[mt][nt2 * 2 + 1];
                mma_bf16(c0, pH[mt][kk][0], pH[mt][kk][1], pH[mt][kk][2], pH[mt][kk][3], bh0, bh1);
                mma_bf16(c1, pH[mt][kk][0], pH[mt][kk][1], pH[mt][kk][2], pH[mt][kk][3], bh2, bh3);
                mma_bf16(c0, pH[mt][kk][0], pH[mt][kk][1], pH[mt][kk][2], pH[mt][kk][3], bl0, bl1);
                mma_bf16(c1, pH[mt][kk][0], pH[mt][kk][1], pH[mt][kk][2], pH[mt][kk][3], bl2, bl3);
                mma_bf16(c0, pL[mt][kk][0], pL[mt][kk][1], pL[mt][kk][2], pL[mt][kk][3], bh0, bh1);
                mma_bf16(c1, pL[mt][kk][0], pL[mt][kk][1], pL[mt][kk][2], pL[mt][kk][3], bh2, bh3);
            }
        }
    }
}

#define ZERO8(po) \
    _Pragma("unroll") for (int mt = 0; mt < 2; ++mt) \
    _Pragma("unroll") for (int nt = 0; nt < 8; ++nt) \
    _Pragma("unroll") for (int e = 0; e < 4; ++e) (po)[mt][nt][e] = 0.0f;
#define ZERO4(a) \
    _Pragma("unroll") for (int mt = 0; mt < 2; ++mt) \
    _Pragma("unroll") for (int nt = 0; nt < 4; ++nt) \
    _Pragma("unroll") for (int e = 0; e < 4; ++e) (a)[mt][nt][e] = 0.0f;

__global__ void __launch_bounds__(128, 3)
ttt_mma_kernel(const float* __restrict__ qkv, float* __restrict__ out) {
    extern __shared__ char sm[];
    const u32 sb = smem_u32(sm);
    const int tid = threadIdx.x, lane = tid & 31, wid = tid >> 5;
    const int wm = wid & 1, wn = wid >> 1;
    const int mbase = wm * 32, nbase = wn * 32;

    const int mb = (NMB - 1) - (int)blockIdx.y;     // heavy T-blocks first
    const int bh = blockIdx.x, b = bh >> 4, h = bh & 15;
    const float* base = qkv + (size_t)b * S_LEN * ROWSTRIDE + h * DIM;
    const float* gQ = base;
    const float* gK = base + NH * DIM;
    const float* gV = base + 2 * NH * DIM;
    const int t0 = mb * BLKM;
    const int nK = mb + 1;                          // 64-row K blocks needed

    // Q tile (scaled by 2), split into smem
    load_split(sm, OFF_Q, gQ + (size_t)t0 * ROWSTRIDE, 2.0f, tid);

    // ================= pass 1: po = partial of tril(2Q K^T) K  (= 2*O2) =================
    float po[2][8][4];
    ZERO8(po);
    for (int j = 0; j < nK; ++j) {
        __syncthreads();                            // sK free (prev gemm2 done)
        load_split(sm, OFF_K, gK + (size_t)j * BLKS * ROWSTRIDE, 1.0f, tid);
        __syncthreads();

        float acc1[2][4][4];
        ZERO4(acc1);
        gemm_nT(sb + OFF_Q, sb + OFF_K, acc1, lane, mbase, nbase);    // 2Q K^T

        u32 pH[2][2][4], pL[2][2][4];
        mask_pack(acc1, pH, pL, lane, t0 + mbase, j * BLKS + nbase, j == nK - 1);

        gemm2_reg(pH, pL, sb + OFF_K, po, lane, nbase);               // += S K
    }

    // cross-warp reduce po (wn pairs) -> -O2 split tiles in sO2
    __syncthreads();
    if (wn == 1) {
#pragma unroll
        for (int mt = 0; mt < 2; ++mt)
#pragma unroll
            for (int nt = 0; nt < 8; ++nt)
#pragma unroll
                for (int rr = 0; rr < 2; ++rr) {
                    int rl = mt * 16 + (lane >> 2) + rr * 8;
                    int col = nt * 8 + ((lane & 3) << 1);
                    float2 v = make_float2(po[mt][nt][rr * 2], po[mt][nt][rr * 2 + 1]);
                    *reinterpret_cast<float2*>(sm + RED_OFF + wm * 8192 + rl * 256 + col * 4) = v;
                }
    }
    __syncthreads();
    if (wn == 0) {
#pragma unroll
        for (int mt = 0; mt < 2; ++mt)
#pragma unroll
            for (int nt = 0; nt < 8; ++nt)
#pragma unroll
                for (int rr = 0; rr < 2; ++rr) {
                    int rl = mt * 16 + (lane >> 2) + rr * 8;
                    int col = nt * 8 + ((lane & 3) << 1);
                    float2 p = *reinterpret_cast<float2*>(sm + RED_OFF + wm * 8192 + rl * 256 + col * 4);
                    float v0 = -0.5f * (po[mt][nt][rr * 2]     + p.x);
                    float v1 = -0.5f * (po[mt][nt][rr * 2 + 1] + p.y);
                    u32 hp, lp;
                    split_pack(v0, v1, hp, lp);
                    u32 o = off64(mbase + rl, col << 1);
                    *reinterpret_cast<u32*>(sm + OFF_O2 + o)      = hp;
                    *reinterpret_cast<u32*>(sm + OFF_O2 + HL + o) = lp;
                }
    }

    // ===== pass 2: po = partial of tril(2Q K^T + (-O2) K^T) V = (2A1 - A2) V =====
    ZERO8(po);
    for (int j = 0; j < nK; ++j) {
        __syncthreads();                            // sK/sV free; sO2/staging settled
        load_split(sm, OFF_K, gK + (size_t)j * BLKS * ROWSTRIDE, 1.0f, tid);
        load_split(sm, OFF_V, gV + (size_t)j * BLKS * ROWSTRIDE, 1.0f, tid);
        __syncthreads();

        float acc1[2][4][4];
        ZERO4(acc1);
        gemm_nT(sb + OFF_Q,  sb + OFF_K, acc1, lane, mbase, nbase);   // 2Q K^T
        gemm_nT(sb + OFF_O2, sb + OFF_K, acc1, lane, mbase, nbase);   // += (-O2) K^T

        u32 pH[2][2][4], pL[2][2][4];
        mask_pack(acc1, pH, pL, lane, t0 + mbase, j * BLKS + nbase, j == nK - 1);

        gemm2_reg(pH, pL, sb + OFF_V, po, lane, nbase);               // += S V
    }

    // cross-warp reduce po -> final out
    __syncthreads();
    if (wn == 1) {
#pragma unroll
        for (int mt = 0; mt < 2; ++mt)
#pragma unroll
            for (int nt = 0; nt < 8; ++nt)
#pragma unroll
                for (int rr = 0; rr < 2; ++rr) {
                    int rl = mt * 16 + (lane >> 2) + rr * 8;
                    int col = nt * 8 + ((lane & 3) << 1);
                    float2 v = make_float2(po[mt][nt][rr * 2], po[mt][nt][rr * 2 + 1]);
                    *reinterpret_cast<float2*>(sm + RED_OFF + wm * 8192 + rl * 256 + col * 4) = v;
                }
    }
    __syncthreads();
    if (wn == 0) {
#pragma unroll
        for (int mt = 0; mt < 2; ++mt)
#pragma unroll
            for (int nt = 0; nt < 8; ++nt)
#pragma unroll
                for (int rr = 0; rr < 2; ++rr) {
                    int rl = mt * 16 + (lane >> 2) + rr * 8;
                    int col = nt * 8 + ((lane & 3) << 1);
                    float2 p = *reinterpret_cast<float2*>(sm + RED_OFF + wm * 8192 + rl * 256 + col * 4);
                    float2 v = make_float2(po[mt][nt][rr * 2] + p.x,
                                           po[mt][nt][rr * 2 + 1] + p.y);
                    size_t off = (((size_t)b * S_LEN + t0 + mbase + rl) * NH + h) * DIM + col;
                    *reinterpret_cast<float2*>(out + off) = v;
                }
    }
}

extern "C" void kernel_launch(void* const* d_in, const int* in_sizes, int n_in,
                              void* d_out, int out_size) {
    const float* qkv = (const float*)d_in[0];
    float* out = (float*)d_out;
    cudaFuncSetAttribute(ttt_mma_kernel, cudaFuncAttributeMaxDynamicSharedMemorySize,
                         SMEM_TOTAL);
    dim3 grid(32 /*b*h*/, NMB /*reversed T-blocks*/);
    ttt_mma_kernel<<<grid, 128, SMEM_TOTAL>>>(qkv, out);
}

// round 10
// speedup vs baseline: 2.0489x; 1.0084x over previous
#include <cuda_runtime.h>
#include <cuda_bf16.h>
#include <cstdint>

typedef uint32_t u32;

#define S_LEN 2048
#define NH 16
#define DIM 64
#define BLKM 64          // T rows per CTA
#define BLKS 64          // K/V rows per j-step
#define NMB 32           // S_LEN / BLKM
#define ROWSTRIDE 3072   // 3*NH*DIM floats between consecutive s rows

#define HL 8192          // one [64][64] bf16 half-tile (hi or lo)
// smem layout (each buffer = hi tile then lo tile, off64 swizzled)
#define OFF_Q   0
#define OFF_K   16384
#define OFF_V   32768    // pass 1: fp32 K staging (16KB); pass 2: V split tiles
#define OFF_O2  49152
#define SMEM_TOTAL 65536               // -> 3 CTAs/SM
#define RED_OFF OFF_K                  // f32 staging for cross-warp reduce (16KB)

// ------------------------------------------------------------------ helpers
__device__ __forceinline__ u32 smem_u32(const void* p) {
    u32 a; asm("{ .reg .u64 t; cvta.to.shared.u64 t, %1; cvt.u32.u64 %0, t; }"
               : "=r"(a) : "l"(p));
    return a;
}
__device__ __forceinline__ u32 off64(int r, int cb) { return (u32)(r * 128 + (cb ^ ((r & 7) << 4))); }

__device__ __forceinline__ void ldsm4(u32 a, u32& r0, u32& r1, u32& r2, u32& r3) {
    asm volatile("ldmatrix.sync.aligned.m8n8.x4.shared.b16 {%0,%1,%2,%3}, [%4];"
        : "=r"(r0), "=r"(r1), "=r"(r2), "=r"(r3) : "r"(a));
}
__device__ __forceinline__ void ldsm4t(u32 a, u32& r0, u32& r1, u32& r2, u32& r3) {
    asm volatile("ldmatrix.sync.aligned.m8n8.x4.trans.shared.b16 {%0,%1,%2,%3}, [%4];"
        : "=r"(r0), "=r"(r1), "=r"(r2), "=r"(r3) : "r"(a));
}
__device__ __forceinline__ void mma_bf16(float* c, u32 a0, u32 a1, u32 a2, u32 a3,
                                         u32 b0, u32 b1) {
    asm volatile("mma.sync.aligned.m16n8k16.row.col.f32.bf16.bf16.f32 "
        "{%0,%1,%2,%3}, {%4,%5,%6,%7}, {%8,%9}, {%0,%1,%2,%3};"
        : "+f"(c[0]), "+f"(c[1]), "+f"(c[2]), "+f"(c[3])
        : "r"(a0), "r"(a1), "r"(a2), "r"(a3), "r"(b0), "r"(b1));
}
// fast truncation split: hi = top16 (PRMT pack), lo = x - hi (rn bf16x2 pack)
__device__ __forceinline__ void split_pack(float v0, float v1, u32& hp, u32& lp) {
    u32 u0 = __float_as_uint(v0), u1 = __float_as_uint(v1);
    asm("prmt.b32 %0, %1, %2, 0x7632;" : "=r"(hp) : "r"(u0), "r"(u1));
    float lo0 = v0 - __uint_as_float(u0 & 0xFFFF0000u);
    float lo1 = v1 - __uint_as_float(u1 & 0xFFFF0000u);
    asm("cvt.rn.satfinite.bf16x2.f32 %0, %1, %2;" : "=r"(lp) : "f"(lo1), "f"(lo0));
}

#define CP_COMMIT() asm volatile("cp.async.commit_group;" ::: "memory")
#define CP_WAIT0()  asm volatile("cp.async.wait_group 0;" ::: "memory")

// ---- cp.async: 64x64 fp32 tile -> fp32 stage at OFF_V (128 thr, 8x16B each) ----
__device__ __forceinline__ void cpasync64(u32 stg, const float* src, int tid) {
#pragma unroll
    for (int it = 0; it < 8; ++it) {
        int f = tid + it * 128;
        int s = f >> 4, dq = (f & 15) << 2;
        u32 dst = stg + (u32)(s * 256 + dq * 4);
        const float* g = src + (size_t)s * ROWSTRIDE + dq;
        asm volatile("cp.async.cg.shared.global [%0], [%1], 16;" :: "r"(dst), "l"(g));
    }
    CP_COMMIT();
}
// ---- convert fp32 stage (OFF_V) -> K split-bf16 tiles ----
__device__ __forceinline__ void convert_stageK(char* sm, int tid) {
#pragma unroll
    for (int it = 0; it < 8; ++it) {
        int f = tid + it * 128;
        int s = f >> 4, dq = (f & 15) << 2;
        float4 v = *reinterpret_cast<const float4*>(sm + OFF_V + s * 256 + dq * 4);
        u32 hp0, lp0, hp1, lp1;
        split_pack(v.x, v.y, hp0, lp0);
        split_pack(v.z, v.w, hp1, lp1);
        u32 o = off64(s, dq << 1);
        *reinterpret_cast<u32*>(sm + OFF_K + o)          = hp0;
        *reinterpret_cast<u32*>(sm + OFF_K + o + 4)      = hp1;
        *reinterpret_cast<u32*>(sm + OFF_K + HL + o)     = lp0;
        *reinterpret_cast<u32*>(sm + OFF_K + HL + o + 4) = lp1;
    }
}

// ---- direct LDG load: 64 x 64 fp32 -> split-bf16 hi/lo swizzled smem (128 thr) ----
__device__ __forceinline__ void load_split(char* sm, int base, const float* src,
                                           float scale, int tid) {
#pragma unroll
    for (int it = 0; it < 8; ++it) {
        int f = tid + it * 128;
        int s = f >> 4, dq = (f & 15) << 2;
        float4 v = *reinterpret_cast<const float4*>(src + (size_t)s * ROWSTRIDE + dq);
        u32 hp0, lp0, hp1, lp1;
        split_pack(v.x * scale, v.y * scale, hp0, lp0);
        split_pack(v.z * scale, v.w * scale, hp1, lp1);
        u32 o = off64(s, dq << 1);
        *reinterpret_cast<u32*>(sm + base + o)          = hp0;
        *reinterpret_cast<u32*>(sm + base + o + 4)      = hp1;
        *reinterpret_cast<u32*>(sm + base + HL + o)     = lp0;
        *reinterpret_cast<u32*>(sm + base + HL + o + 4) = lp1;
    }
}

// ---- GEMM1: acc[32x32 slice] += A[64x64] * (B[64x64])^T, 3-term split ----
__device__ __forceinline__ void gemm_nT(u32 aHi, u32 bHi, float (&acc)[2][4][4],
                                        int lane, int mbase, int nbase) {
    const int arL = lane & 15, acL = (lane >> 4) << 4;
    const int brL = ((lane >> 4) << 3) + (lane & 7), bcL = ((lane >> 3) & 1) << 4;
#pragma unroll
    for (int kk = 0; kk < 4; ++kk) {
        const int kb = kk << 5;
        u32 aH[2][4], aL[2][4];
#pragma unroll
        for (int mt = 0; mt < 2; ++mt) {
            u32 ad = aHi + off64(mbase + mt * 16 + arL, kb + acL);
            ldsm4(ad,      aH[mt][0], aH[mt][1], aH[mt][2], aH[mt][3]);
            ldsm4(ad + HL, aL[mt][0], aL[mt][1], aL[mt][2], aL[mt][3]);
        }
#pragma unroll
        for (int nt2 = 0; nt2 < 2; ++nt2) {
            u32 bd = bHi + off64(nbase + nt2 * 16 + brL, kb + bcL);
            u32 bh0, bh1, bh2, bh3, bl0, bl1, bl2, bl3;
            ldsm4(bd,      bh0, bh1, bh2, bh3);
            ldsm4(bd + HL, bl0, bl1, bl2, bl3);
#pragma unroll
            for (int mt = 0; mt < 2; ++mt) {
                float* c0 = acc[mt][nt2 * 2];
                float* c1 = acc[mt][nt2 * 2 + 1];
                mma_bf16(c0, aH[mt][0], aH[mt][1], aH[mt][2], aH[mt][3], bh0, bh1);
                mma_bf16(c1, aH[mt][0], aH[mt][1], aH[mt][2], aH[mt][3], bh2, bh3);
                mma_bf16(c0, aH[mt][0], aH[mt][1], aH[mt][2], aH[mt][3], bl0, bl1);
                mma_bf16(c1, aH[mt][0], aH[mt][1], aH[mt][2], aH[mt][3], bl2, bl3);
                mma_bf16(c0, aL[mt][0], aL[mt][1], aL[mt][2], aL[mt][3], bh0, bh1);
                mma_bf16(c1, aL[mt][0], aL[mt][1], aL[mt][2], aL[mt][3], bh2, bh3);
            }
        }
    }
}

// ---- fused dual GEMM1: acc += A0*B^T + A1*B^T with B fragments loaded ONCE ----
__device__ __forceinline__ void gemm_nT2(u32 aHi0, u32 aHi1, u32 bHi, float (&acc)[2][4][4],
                                         int lane, int mbase, int nbase) {
    const int arL = lane & 15, acL = (lane >> 4) << 4;
    const int brL = ((lane >> 4) << 3) + (lane & 7), bcL = ((lane >> 3) & 1) << 4;
#pragma unroll
    for (int kk = 0; kk < 4; ++kk) {
        const int kb = kk << 5;
        u32 bh[2][4], bl[2][4];
#pragma unroll
        for (int nt2 = 0; nt2 < 2; ++nt2) {
            u32 bd = bHi + off64(nbase + nt2 * 16 + brL, kb + bcL);
            ldsm4(bd,      bh[nt2][0], bh[nt2][1], bh[nt2][2], bh[nt2][3]);
            ldsm4(bd + HL, bl[nt2][0], bl[nt2][1], bl[nt2][2], bl[nt2][3]);
        }
#pragma unroll
        for (int as = 0; as < 2; ++as) {
            const u32 aHi = as ? aHi1 : aHi0;
            u32 aH[2][4], aL[2][4];
#pragma unroll
            for (int mt = 0; mt < 2; ++mt) {
                u32 ad = aHi + off64(mbase + mt * 16 + arL, kb + acL);
                ldsm4(ad,      aH[mt][0], aH[mt][1], aH[mt][2], aH[mt][3]);
                ldsm4(ad + HL, aL[mt][0], aL[mt][1], aL[mt][2], aL[mt][3]);
            }
#pragma unroll
            for (int nt2 = 0; nt2 < 2; ++nt2) {
#pragma unroll
                for (int mt = 0; mt < 2; ++mt) {
                    float* c0 = acc[mt][nt2 * 2];
                    float* c1 = acc[mt][nt2 * 2 + 1];
                    mma_bf16(c0, aH[mt][0], aH[mt][1], aH[mt][2], aH[mt][3], bh[nt2][0], bh[nt2][1]);
                    mma_bf16(c1, aH[mt][0], aH[mt][1], aH[mt][2], aH[mt][3], bh[nt2][2], bh[nt2][3]);
                    mma_bf16(c0, aH[mt][0], aH[mt][1], aH[mt][2], aH[mt][3], bl[nt2][0], bl[nt2][1]);
                    mma_bf16(c1, aH[mt][0], aH[mt][1], aH[mt][2], aH[mt][3], bl[nt2][2], bl[nt2][3]);
                    mma_bf16(c0, aL[mt][0], aL[mt][1], aL[mt][2], aL[mt][3], bh[nt2][0], bh[nt2][1]);
                    mma_bf16(c1, aL[mt][0], aL[mt][1], aL[mt][2], aL[mt][3], bh[nt2][2], bh[nt2][3]);
                }
            }
        }
    }
}

// ---- mask (absolute row/col) + in-register split into A-operand packs ----
__device__ __forceinline__ void mask_pack(float (&acc)[2][4][4],
                                          u32 (&pH)[2][2][4], u32 (&pL)[2][2][4],
                                          int lane, int rowAbs0, int colAbs0, bool diag) {
    if (diag) {
#pragma unroll
        for (int mt = 0; mt < 2; ++mt)
#pragma unroll
            for (int nt = 0; nt < 4; ++nt) {
                int col = colAbs0 + nt * 8 + ((lane & 3) << 1);
#pragma unroll
                for (int rr = 0; rr < 2; ++rr) {
                    int row = rowAbs0 + mt * 16 + (lane >> 2) + rr * 8;
                    if (col     > row) acc[mt][nt][rr * 2 + 0] = 0.0f;
                    if (col + 1 > row) acc[mt][nt][rr * 2 + 1] = 0.0f;
                }
            }
    }
#pragma unroll
    for (int mt = 0; mt < 2; ++mt)
#pragma unroll
        for (int kk = 0; kk < 2; ++kk) {
            split_pack(acc[mt][2*kk  ][0], acc[mt][2*kk  ][1], pH[mt][kk][0], pL[mt][kk][0]);
            split_pack(acc[mt][2*kk  ][2], acc[mt][2*kk  ][3], pH[mt][kk][1], pL[mt][kk][1]);
            split_pack(acc[mt][2*kk+1][0], acc[mt][2*kk+1][1], pH[mt][kk][2], pL[mt][kk][2]);
            split_pack(acc[mt][2*kk+1][2], acc[mt][2*kk+1][3], pH[mt][kk][3], pL[mt][kk][3]);
        }
}

// ---- GEMM2: po[32x64] += S_slice(regs, 32 k) * B[k-slice x 64], B via ldmatrix.trans ----
__device__ __forceinline__ void gemm2_reg(const u32 (&pH)[2][2][4], const u32 (&pL)[2][2][4],
                                          u32 bHi, float (&po)[2][8][4],
                                          int lane, int kbase) {
    const int brL = (((lane >> 3) & 1) << 3) + (lane & 7), bcL = (lane >> 4) << 4;
#pragma unroll
    for (int kk = 0; kk < 2; ++kk) {
#pragma unroll
        for (int nt2 = 0; nt2 < 4; ++nt2) {
            u32 bd = bHi + off64(kbase + kk * 16 + brL, (nt2 << 5) + bcL);
            u32 bh0, bh1, bh2, bh3, bl0, bl1, bl2, bl3;
            ldsm4t(bd,      bh0, bh1, bh2, bh3);
            ldsm4t(bd + HL, bl0, bl1, bl2, bl3);
#pragma unroll
            for (int mt = 0; mt < 2; ++mt) {
                float* c0 = po[mt][nt2 * 2];
                float* c1 = po[mt][nt2 * 2 + 1];
                mma_bf16(c0, pH[mt][kk][0], pH[mt][kk][1], pH[mt][kk][2], pH[mt][kk][3], bh0, bh1);
                mma_bf16(c1, pH[mt][kk][0], pH[mt][kk][1], pH[mt][kk][2], pH[mt][kk][3], bh2, bh3);
                mma_bf16(c0, pH[mt][kk][0], pH[mt][kk][1], pH[mt][kk][2], pH[mt][kk][3], bl0, bl1);
                mma_bf16(c1, pH[mt][kk][0], pH[mt][kk][1], pH[mt][kk][2], pH[mt][kk][3], bl2, bl3);
                mma_bf16(c0, pL[mt][kk][0], pL[mt][kk][1], pL[mt][kk][2], pL[mt][kk][3], bh0, bh1);
                mma_bf16(c1, pL[mt][kk][0], pL[mt][kk][1], pL[mt][kk][2], pL[mt][kk][3], bh2, bh3);
            }
        }
    }
}

#define ZERO8(po) \
    _Pragma("unroll") for (int mt = 0; mt < 2; ++mt) \
    _Pragma("unroll") for (int nt = 0; nt < 8; ++nt) \
    _Pragma("unroll") for (int e = 0; e < 4; ++e) (po)[mt][nt][e] = 0.0f;
#define ZERO4(a) \
    _Pragma("unroll") for (int mt = 0; mt < 2; ++mt) \
    _Pragma("unroll") for (int nt = 0; nt < 4; ++nt) \
    _Pragma("unroll") for (int e = 0; e < 4; ++e) (a)[mt][nt][e] = 0.0f;

__global__ void __launch_bounds__(128, 3)
ttt_mma_kernel(const float* __restrict__ qkv, float* __restrict__ out) {
    extern __shared__ char sm[];
    const u32 sb = smem_u32(sm);
    const int tid = threadIdx.x, lane = tid & 31, wid = tid >> 5;
    const int wm = wid & 1, wn = wid >> 1;
    const int mbase = wm * 32, nbase = wn * 32;

    const int mb = (NMB - 1) - (int)blockIdx.y;     // heavy T-blocks first
    const int bh = blockIdx.x, b = bh >> 4, h = bh & 15;
    const float* base = qkv + (size_t)b * S_LEN * ROWSTRIDE + h * DIM;
    const float* gQ = base;
    const float* gK = base + NH * DIM;
    const float* gV = base + 2 * NH * DIM;
    const int t0 = mb * BLKM;
    const int nK = mb + 1;                          // 64-row K blocks needed
    // on the diagonal block, warp (wm=0, wn=1) computes a fully-masked quadrant
    const bool diagDead = (wm == 0 && wn == 1);

    // kick K0 -> fp32 stage (V buffer, free in pass 1); Q LDG overlaps the copy
    cpasync64(sb + OFF_V, gK, tid);
    load_split(sm, OFF_Q, gQ + (size_t)t0 * ROWSTRIDE, 2.0f, tid);

    // ================= pass 1: po = partial of tril(2Q K^T) K  (= 2*O2) =================
    float po[2][8][4];
    ZERO8(po);
    for (int j = 0; j < nK; ++j) {
        CP_WAIT0(); __syncthreads();                // stage holds K_j; prev gemm2 done with sK
        convert_stageK(sm, tid);                    // K_j -> split bf16 (LDS, not LDG)
        __syncthreads();                            // sK visible; stage free
        if (j + 1 < nK)
            cpasync64(sb + OFF_V, gK + (size_t)(j + 1) * BLKS * ROWSTRIDE, tid);

        if (!(j == nK - 1 && diagDead)) {
            float acc1[2][4][4];
            ZERO4(acc1);
            gemm_nT(sb + OFF_Q, sb + OFF_K, acc1, lane, mbase, nbase);  // 2Q K^T
            u32 pH[2][2][4], pL[2][2][4];
            mask_pack(acc1, pH, pL, lane, t0 + mbase, j * BLKS + nbase, j == nK - 1);
            gemm2_reg(pH, pL, sb + OFF_K, po, lane, nbase);             // += S K
        }
    }

    // cross-warp reduce po (wn pairs) -> -O2 split tiles in sO2
    __syncthreads();
    if (wn == 1) {
#pragma unroll
        for (int mt = 0; mt < 2; ++mt)
#pragma unroll
            for (int nt = 0; nt < 8; ++nt)
#pragma unroll
                for (int rr = 0; rr < 2; ++rr) {
                    int rl = mt * 16 + (lane >> 2) + rr * 8;
                    int col = nt * 8 + ((lane & 3) << 1);
                    float2 v = make_float2(po[mt][nt][rr * 2], po[mt][nt][rr * 2 + 1]);
                    *reinterpret_cast<float2*>(sm + RED_OFF + wm * 8192 + rl * 256 + col * 4) = v;
                }
    }
    __syncthreads();
    if (wn == 0) {
#pragma unroll
        for (int mt = 0; mt < 2; ++mt)
#pragma unroll
            for (int nt = 0; nt < 8; ++nt)
#pragma unroll
                for (int rr = 0; rr < 2; ++rr) {
                    int rl = mt * 16 + (lane >> 2) + rr * 8;
                    int col = nt * 8 + ((lane & 3) << 1);
                    float2 p = *reinterpret_cast<float2*>(sm + RED_OFF + wm * 8192 + rl * 256 + col * 4);
                    float v0 = -0.5f * (po[mt][nt][rr * 2]     + p.x);
                    float v1 = -0.5f * (po[mt][nt][rr * 2 + 1] + p.y);
                    u32 hp, lp;
                    split_pack(v0, v1, hp, lp);
                    u32 o = off64(mbase + rl, col << 1);
                    *reinterpret_cast<u32*>(sm + OFF_O2 + o)      = hp;
                    *reinterpret_cast<u32*>(sm + OFF_O2 + HL + o) = lp;
                }
    }

    // ===== pass 2: po = partial of tril(2Q K^T + (-O2) K^T) V = (2A1 - A2) V =====
    ZERO8(po);
    for (int j = 0; j < nK; ++j) {
        __syncthreads();                            // sK/sV free; sO2/staging settled
        load_split(sm, OFF_K, gK + (size_t)j * BLKS * ROWSTRIDE, 1.0f, tid);
        load_split(sm, OFF_V, gV + (size_t)j * BLKS * ROWSTRIDE, 1.0f, tid);
        __syncthreads();

        if (!(j == nK - 1 && diagDead)) {
            float acc1[2][4][4];
            ZERO4(acc1);
            gemm_nT2(sb + OFF_Q, sb + OFF_O2, sb + OFF_K, acc1, lane, mbase, nbase);

            u32 pH[2][2][4], pL[2][2][4];
            mask_pack(acc1, pH, pL, lane, t0 + mbase, j * BLKS + nbase, j == nK - 1);

            gemm2_reg(pH, pL, sb + OFF_V, po, lane, nbase);             // += S V
        }
    }

    // cross-warp reduce po -> final out
    __syncthreads();
    if (wn == 1) {
#pragma unroll
        for (int mt = 0; mt < 2; ++mt)
#pragma unroll
            for (int nt = 0; nt < 8; ++nt)
#pragma unroll
                for (int rr = 0; rr < 2; ++rr) {
                    int rl = mt * 16 + (lane >> 2) + rr * 8;
                    int col = nt * 8 + ((lane & 3) << 1);
                    float2 v = make_float2(po[mt][nt][rr * 2], po[mt][nt][rr * 2 + 1]);
                    *reinterpret_cast<float2*>(sm + RED_OFF + wm * 8192 + rl * 256 + col * 4) = v;
                }
    }
    __syncthreads();
    if (wn == 0) {
#pragma unroll
        for (int mt = 0; mt < 2; ++mt)
#pragma unroll
            for (int nt = 0; nt < 8; ++nt)
#pragma unroll
                for (int rr = 0; rr < 2; ++rr) {
                    int rl = mt * 16 + (lane >> 2) + rr * 8;
                    int col = nt * 8 + ((lane & 3) << 1);
                    float2 p = *reinterpret_cast<float2*>(sm + RED_OFF + wm * 8192 + rl * 256 + col * 4);
                    float2 v = make_float2(po[mt][nt][rr * 2] + p.x,
                                           po[mt][nt][rr * 2 + 1] + p.y);
                    size_t off = (((size_t)b * S_LEN + t0 + mbase + rl) * NH + h) * DIM + col;
                    *reinterpret_cast<float2*>(out + off) = v;
                }
    }
}

extern "C" void kernel_launch(void* const* d_in, const int* in_sizes, int n_in,
                              void* d_out, int out_size) {
    const float* qkv = (const float*)d_in[0];
    float* out = (float*)d_out;
    cudaFuncSetAttribute(ttt_mma_kernel, cudaFuncAttributeMaxDynamicSharedMemorySize,
                         SMEM_TOTAL);
    dim3 grid(32 /*b*h*/, NMB /*reversed T-blocks*/);
    ttt_mma_kernel<<<grid, 128, SMEM_TOTAL>>>(qkv, out);
}

// round 11
// speedup vs baseline: 2.1200x; 1.0347x over previous
#include <cuda_runtime.h>
#include <cuda_bf16.h>
#include <cstdint>

typedef uint32_t u32;

#define S_LEN 2048
#define NH 16
#define DIM 64
#define BLKM 64          // T rows per CTA
#define BLKS 64          // K/V rows per j-step
#define NMB 32           // S_LEN / BLKM
#define ROWSTRIDE 3072   // 3*NH*DIM floats between consecutive s rows

#define HL 8192          // one [64][64] bf16 half-tile (hi or lo)
// smem layout (each buffer = hi tile then lo tile, off64 swizzled)
#define OFF_Q   0
#define OFF_K   16384
#define OFF_V   32768    // pass 1: fp32 K staging (16KB); pass 2: V split tiles
#define OFF_O2  49152
#define SMEM_TOTAL 65536               // -> 3 CTAs/SM
#define RED_OFF OFF_K                  // f32 staging for cross-warp reduce (16KB)

#define NTILE 528                      // sum_{mb} (mb+1)
// A1 tile cache: [bh][tri(mb)+j][4096 floats]. Written pass 1, read pass 2 by
// the SAME thread at the SAME addresses -> no fence needed. ~277 MB.
__device__ float g_s1[(size_t)32 * NTILE * 4096];

// ------------------------------------------------------------------ helpers
__device__ __forceinline__ u32 smem_u32(const void* p) {
    u32 a; asm("{ .reg .u64 t; cvta.to.shared.u64 t, %1; cvt.u32.u64 %0, t; }"
               : "=r"(a) : "l"(p));
    return a;
}
__device__ __forceinline__ u32 off64(int r, int cb) { return (u32)(r * 128 + (cb ^ ((r & 7) << 4))); }

__device__ __forceinline__ void ldsm4(u32 a, u32& r0, u32& r1, u32& r2, u32& r3) {
    asm volatile("ldmatrix.sync.aligned.m8n8.x4.shared.b16 {%0,%1,%2,%3}, [%4];"
        : "=r"(r0), "=r"(r1), "=r"(r2), "=r"(r3) : "r"(a));
}
__device__ __forceinline__ void ldsm4t(u32 a, u32& r0, u32& r1, u32& r2, u32& r3) {
    asm volatile("ldmatrix.sync.aligned.m8n8.x4.trans.shared.b16 {%0,%1,%2,%3}, [%4];"
        : "=r"(r0), "=r"(r1), "=r"(r2), "=r"(r3) : "r"(a));
}
__device__ __forceinline__ void mma_bf16(float* c, u32 a0, u32 a1, u32 a2, u32 a3,
                                         u32 b0, u32 b1) {
    asm volatile("mma.sync.aligned.m16n8k16.row.col.f32.bf16.bf16.f32 "
        "{%0,%1,%2,%3}, {%4,%5,%6,%7}, {%8,%9}, {%0,%1,%2,%3};"
        : "+f"(c[0]), "+f"(c[1]), "+f"(c[2]), "+f"(c[3])
        : "r"(a0), "r"(a1), "r"(a2), "r"(a3), "r"(b0), "r"(b1));
}
// fast truncation split: hi = top16 (PRMT pack), lo = x - hi (rn bf16x2 pack)
__device__ __forceinline__ void split_pack(float v0, float v1, u32& hp, u32& lp) {
    u32 u0 = __float_as_uint(v0), u1 = __float_as_uint(v1);
    asm("prmt.b32 %0, %1, %2, 0x7632;" : "=r"(hp) : "r"(u0), "r"(u1));
    float lo0 = v0 - __uint_as_float(u0 & 0xFFFF0000u);
    float lo1 = v1 - __uint_as_float(u1 & 0xFFFF0000u);
    asm("cvt.rn.satfinite.bf16x2.f32 %0, %1, %2;" : "=r"(lp) : "f"(lo1), "f"(lo0));
}

#define CP_COMMIT() asm volatile("cp.async.commit_group;" ::: "memory")
#define CP_WAIT0()  asm volatile("cp.async.wait_group 0;" ::: "memory")

// ---- cp.async: 64x64 fp32 tile -> fp32 stage at OFF_V (128 thr, 8x16B each) ----
__device__ __forceinline__ void cpasync64(u32 stg, const float* src, int tid) {
#pragma unroll
    for (int it = 0; it < 8; ++it) {
        int f = tid + it * 128;
        int s = f >> 4, dq = (f & 15) << 2;
        u32 dst = stg + (u32)(s * 256 + dq * 4);
        const float* g = src + (size_t)s * ROWSTRIDE + dq;
        asm volatile("cp.async.cg.shared.global [%0], [%1], 16;" :: "r"(dst), "l"(g));
    }
    CP_COMMIT();
}
// ---- convert fp32 stage (OFF_V) -> K split-bf16 tiles ----
__device__ __forceinline__ void convert_stageK(char* sm, int tid) {
#pragma unroll
    for (int it = 0; it < 8; ++it) {
        int f = tid + it * 128;
        int s = f >> 4, dq = (f & 15) << 2;
        float4 v = *reinterpret_cast<const float4*>(sm + OFF_V + s * 256 + dq * 4);
        u32 hp0, lp0, hp1, lp1;
        split_pack(v.x, v.y, hp0, lp0);
        split_pack(v.z, v.w, hp1, lp1);
        u32 o = off64(s, dq << 1);
        *reinterpret_cast<u32*>(sm + OFF_K + o)          = hp0;
        *reinterpret_cast<u32*>(sm + OFF_K + o + 4)      = hp1;
        *reinterpret_cast<u32*>(sm + OFF_K + HL + o)     = lp0;
        *reinterpret_cast<u32*>(sm + OFF_K + HL + o + 4) = lp1;
    }
}

// ---- direct LDG load: 64 x 64 fp32 -> split-bf16 hi/lo swizzled smem (128 thr) ----
__device__ __forceinline__ void load_split(char* sm, int base, const float* src,
                                           float scale, int tid) {
#pragma unroll
    for (int it = 0; it < 8; ++it) {
        int f = tid + it * 128;
        int s = f >> 4, dq = (f & 15) << 2;
        float4 v = *reinterpret_cast<const float4*>(src + (size_t)s * ROWSTRIDE + dq);
        u32 hp0, lp0, hp1, lp1;
        split_pack(v.x * scale, v.y * scale, hp0, lp0);
        split_pack(v.z * scale, v.w * scale, hp1, lp1);
        u32 o = off64(s, dq << 1);
        *reinterpret_cast<u32*>(sm + base + o)          = hp0;
        *reinterpret_cast<u32*>(sm + base + o + 4)      = hp1;
        *reinterpret_cast<u32*>(sm + base + HL + o)     = lp0;
        *reinterpret_cast<u32*>(sm + base + HL + o + 4) = lp1;
    }
}

// ---- GEMM1: acc[32x32 slice] += A[64x64] * (B[64x64])^T, 3-term split ----
__device__ __forceinline__ void gemm_nT(u32 aHi, u32 bHi, float (&acc)[2][4][4],
                                        int lane, int mbase, int nbase) {
    const int arL = lane & 15, acL = (lane >> 4) << 4;
    const int brL = ((lane >> 4) << 3) + (lane & 7), bcL = ((lane >> 3) & 1) << 4;
#pragma unroll
    for (int kk = 0; kk < 4; ++kk) {
        const int kb = kk << 5;
        u32 aH[2][4], aL[2][4];
#pragma unroll
        for (int mt = 0; mt < 2; ++mt) {
            u32 ad = aHi + off64(mbase + mt * 16 + arL, kb + acL);
            ldsm4(ad,      aH[mt][0], aH[mt][1], aH[mt][2], aH[mt][3]);
            ldsm4(ad + HL, aL[mt][0], aL[mt][1], aL[mt][2], aL[mt][3]);
        }
#pragma unroll
        for (int nt2 = 0; nt2 < 2; ++nt2) {
            u32 bd = bHi + off64(nbase + nt2 * 16 + brL, kb + bcL);
            u32 bh0, bh1, bh2, bh3, bl0, bl1, bl2, bl3;
            ldsm4(bd,      bh0, bh1, bh2, bh3);
            ldsm4(bd + HL, bl0, bl1, bl2, bl3);
#pragma unroll
            for (int mt = 0; mt < 2; ++mt) {
                float* c0 = acc[mt][nt2 * 2];
                float* c1 = acc[mt][nt2 * 2 + 1];
                mma_bf16(c0, aH[mt][0], aH[mt][1], aH[mt][2], aH[mt][3], bh0, bh1);
                mma_bf16(c1, aH[mt][0], aH[mt][1], aH[mt][2], aH[mt][3], bh2, bh3);
                mma_bf16(c0, aH[mt][0], aH[mt][1], aH[mt][2], aH[mt][3], bl0, bl1);
                mma_bf16(c1, aH[mt][0], aH[mt][1], aH[mt][2], aH[mt][3], bl2, bl3);
                mma_bf16(c0, aL[mt][0], aL[mt][1], aL[mt][2], aL[mt][3], bh0, bh1);
                mma_bf16(c1, aL[mt][0], aL[mt][1], aL[mt][2], aL[mt][3], bh2, bh3);
            }
        }
    }
}

// ---- mask (absolute row/col) + in-register split into A-operand packs ----
__device__ __forceinline__ void mask_pack(float (&acc)[2][4][4],
                                          u32 (&pH)[2][2][4], u32 (&pL)[2][2][4],
                                          int lane, int rowAbs0, int colAbs0, bool diag) {
    if (diag) {
#pragma unroll
        for (int mt = 0; mt < 2; ++mt)
#pragma unroll
            for (int nt = 0; nt < 4; ++nt) {
                int col = colAbs0 + nt * 8 + ((lane & 3) << 1);
#pragma unroll
                for (int rr = 0; rr < 2; ++rr) {
                    int row = rowAbs0 + mt * 16 + (lane >> 2) + rr * 8;
                    if (col     > row) acc[mt][nt][rr * 2 + 0] = 0.0f;
                    if (col + 1 > row) acc[mt][nt][rr * 2 + 1] = 0.0f;
                }
            }
    }
#pragma unroll
    for (int mt = 0; mt < 2; ++mt)
#pragma unroll
        for (int kk = 0; kk < 2; ++kk) {
            split_pack(acc[mt][2*kk  ][0], acc[mt][2*kk  ][1], pH[mt][kk][0], pL[mt][kk][0]);
            split_pack(acc[mt][2*kk  ][2], acc[mt][2*kk  ][3], pH[mt][kk][1], pL[mt][kk][1]);
            split_pack(acc[mt][2*kk+1][0], acc[mt][2*kk+1][1], pH[mt][kk][2], pL[mt][kk][2]);
            split_pack(acc[mt][2*kk+1][2], acc[mt][2*kk+1][3], pH[mt][kk][3], pL[mt][kk][3]);
        }
}

// ---- GEMM2: po[32x64] += S_slice(regs, 32 k) * B[k-slice x 64], B via ldmatrix.trans ----
__device__ __forceinline__ void gemm2_reg(const u32 (&pH)[2][2][4], const u32 (&pL)[2][2][4],
                                          u32 bHi, float (&po)[2][8][4],
                                          int lane, int kbase) {
    const int brL = (((lane >> 3) & 1) << 3) + (lane & 7), bcL = (lane >> 4) << 4;
#pragma unroll
    for (int kk = 0; kk < 2; ++kk) {
#pragma unroll
        for (int nt2 = 0; nt2 < 4; ++nt2) {
            u32 bd = bHi + off64(kbase + kk * 16 + brL, (nt2 << 5) + bcL);
            u32 bh0, bh1, bh2, bh3, bl0, bl1, bl2, bl3;
            ldsm4t(bd,      bh0, bh1, bh2, bh3);
            ldsm4t(bd + HL, bl0, bl1, bl2, bl3);
#pragma unroll
            for (int mt = 0; mt < 2; ++mt) {
                float* c0 = po[mt][nt2 * 2];
                float* c1 = po[mt][nt2 * 2 + 1];
                mma_bf16(c0, pH[mt][kk][0], pH[mt][kk][1], pH[mt][kk][2], pH[mt][kk][3], bh0, bh1);
                mma_bf16(c1, pH[mt][kk][0], pH[mt][kk][1], pH[mt][kk][2], pH[mt][kk][3], bh2, bh3);
                mma_bf16(c0, pH[mt][kk][0], pH[mt][kk][1], pH[mt][kk][2], pH[mt][kk][3], bl0, bl1);
                mma_bf16(c1, pH[mt][kk][0], pH[mt][kk][1], pH[mt][kk][2], pH[mt][kk][3], bl2, bl3);
                mma_bf16(c0, pL[mt][kk][0], pL[mt][kk][1], pL[mt][kk][2], pL[mt][kk][3], bh0, bh1);
                mma_bf16(c1, pL[mt][kk][0], pL[mt][kk][1], pL[mt][kk][2], pL[mt][kk][3], bh2, bh3);
            }
        }
    }
}

#define ZERO8(po) \
    _Pragma("unroll") for (int mt = 0; mt < 2; ++mt) \
    _Pragma("unroll") for (int nt = 0; nt < 8; ++nt) \
    _Pragma("unroll") for (int e = 0; e < 4; ++e) (po)[mt][nt][e] = 0.0f;
#define ZERO4(a) \
    _Pragma("unroll") for (int mt = 0; mt < 2; ++mt) \
    _Pragma("unroll") for (int nt = 0; nt < 4; ++nt) \
    _Pragma("unroll") for (int e = 0; e < 4; ++e) (a)[mt][nt][e] = 0.0f;

__global__ void __launch_bounds__(128, 3)
ttt_mma_kernel(const float* __restrict__ qkv, float* __restrict__ out) {
    extern __shared__ char sm[];
    const u32 sb = smem_u32(sm);
    const int tid = threadIdx.x, lane = tid & 31, wid = tid >> 5;
    const int wm = wid & 1, wn = wid >> 1;
    const int mbase = wm * 32, nbase = wn * 32;

    const int mb = (NMB - 1) - (int)blockIdx.y;     // heavy T-blocks first
    const int bh = blockIdx.x, b = bh >> 4, h = bh & 15;
    const float* base = qkv + (size_t)b * S_LEN * ROWSTRIDE + h * DIM;
    const float* gQ = base;
    const float* gK = base + NH * DIM;
    const float* gV = base + 2 * NH * DIM;
    const int t0 = mb * BLKM;
    const int nK = mb + 1;                          // 64-row K blocks needed
    const bool diagDead = (wm == 0 && wn == 1);     // fully-masked diag quadrant
    // per-thread scratch base (coalesced: element i of thread t at i*512 + t*4 floats)
    float* scr0 = g_s1 + ((size_t)(bh * NTILE + (mb * (mb + 1)) / 2) << 12) + (tid << 2);

    // kick K0 -> fp32 stage (V buffer, free in pass 1); Q LDG overlaps the copy
    cpasync64(sb + OFF_V, gK, tid);
    load_split(sm, OFF_Q, gQ + (size_t)t0 * ROWSTRIDE, 2.0f, tid);

    // ================= pass 1: po = partial of tril(2Q K^T) K  (= 2*O2) =================
    float po[2][8][4];
    ZERO8(po);
    for (int j = 0; j < nK; ++j) {
        CP_WAIT0(); __syncthreads();                // stage holds K_j; prev gemm2 done with sK
        convert_stageK(sm, tid);                    // K_j -> split bf16 (LDS, not LDG)
        __syncthreads();                            // sK visible; stage free
        if (j + 1 < nK)
            cpasync64(sb + OFF_V, gK + (size_t)(j + 1) * BLKS * ROWSTRIDE, tid);

        if (!(j == nK - 1 && diagDead)) {
            float acc1[2][4][4];
            ZERO4(acc1);
            gemm_nT(sb + OFF_Q, sb + OFF_K, acc1, lane, mbase, nbase);  // 2Q K^T
            // store raw A1' tile to scratch (pre-mask) for pass 2 reuse
            {
                float* sp = scr0 + ((size_t)j << 12);
                const float* a = &acc1[0][0][0];
#pragma unroll
                for (int i = 0; i < 8; ++i)
                    *reinterpret_cast<float4*>(sp + i * 512) =
                        make_float4(a[i*4], a[i*4+1], a[i*4+2], a[i*4+3]);
            }
            u32 pH[2][2][4], pL[2][2][4];
            mask_pack(acc1, pH, pL, lane, t0 + mbase, j * BLKS + nbase, j == nK - 1);
            gemm2_reg(pH, pL, sb + OFF_K, po, lane, nbase);             // += S K
        }
    }

    // cross-warp reduce po (wn pairs) -> -O2 split tiles in sO2
    __syncthreads();
    if (wn == 1) {
#pragma unroll
        for (int mt = 0; mt < 2; ++mt)
#pragma unroll
            for (int nt = 0; nt < 8; ++nt)
#pragma unroll
                for (int rr = 0; rr < 2; ++rr) {
                    int rl = mt * 16 + (lane >> 2) + rr * 8;
                    int col = nt * 8 + ((lane & 3) << 1);
                    float2 v = make_float2(po[mt][nt][rr * 2], po[mt][nt][rr * 2 + 1]);
                    *reinterpret_cast<float2*>(sm + RED_OFF + wm * 8192 + rl * 256 + col * 4) = v;
                }
    }
    __syncthreads();
    if (wn == 0) {
#pragma unroll
        for (int mt = 0; mt < 2; ++mt)
#pragma unroll
            for (int nt = 0; nt < 8; ++nt)
#pragma unroll
                for (int rr = 0; rr < 2; ++rr) {
                    int rl = mt * 16 + (lane >> 2) + rr * 8;
                    int col = nt * 8 + ((lane & 3) << 1);
                    float2 p = *reinterpret_cast<float2*>(sm + RED_OFF + wm * 8192 + rl * 256 + col * 4);
                    float v0 = -0.5f * (po[mt][nt][rr * 2]     + p.x);
                    float v1 = -0.5f * (po[mt][nt][rr * 2 + 1] + p.y);
                    u32 hp, lp;
                    split_pack(v0, v1, hp, lp);
                    u32 o = off64(mbase + rl, col << 1);
                    *reinterpret_cast<u32*>(sm + OFF_O2 + o)      = hp;
                    *reinterpret_cast<u32*>(sm + OFF_O2 + HL + o) = lp;
                }
    }

    // ===== pass 2: po = partial of tril(A1' + (-O2) K^T) V = (2A1 - A2) V =====
    ZERO8(po);
    for (int j = 0; j < nK; ++j) {
        const bool active = !(j == nK - 1 && diagDead);
        float acc1[2][4][4];
        if (active) {                               // reload A1' tile (latency hides
            float* sp = scr0 + ((size_t)j << 12);   //  under load_split below)
            float* a = &acc1[0][0][0];
#pragma unroll
            for (int i = 0; i < 8; ++i) {
                float4 v = *reinterpret_cast<const float4*>(sp + i * 512);
                a[i*4] = v.x; a[i*4+1] = v.y; a[i*4+2] = v.z; a[i*4+3] = v.w;
            }
        }

        __syncthreads();                            // sK/sV free; sO2/staging settled
        load_split(sm, OFF_K, gK + (size_t)j * BLKS * ROWSTRIDE, 1.0f, tid);
        load_split(sm, OFF_V, gV + (size_t)j * BLKS * ROWSTRIDE, 1.0f, tid);
        __syncthreads();

        if (active) {
            gemm_nT(sb + OFF_O2, sb + OFF_K, acc1, lane, mbase, nbase);  // += (-O2) K^T

            u32 pH[2][2][4], pL[2][2][4];
            mask_pack(acc1, pH, pL, lane, t0 + mbase, j * BLKS + nbase, j == nK - 1);

            gemm2_reg(pH, pL, sb + OFF_V, po, lane, nbase);              // += S V
        }
    }

    // cross-warp reduce po -> final out
    __syncthreads();
    if (wn == 1) {
#pragma unroll
        for (int mt = 0; mt < 2; ++mt)
#pragma unroll
            for (int nt = 0; nt < 8; ++nt)
#pragma unroll
                for (int rr = 0; rr < 2; ++rr) {
                    int rl = mt * 16 + (lane >> 2) + rr * 8;
                    int col = nt * 8 + ((lane & 3) << 1);
                    float2 v = make_float2(po[mt][nt][rr * 2], po[mt][nt][rr * 2 + 1]);
                    *reinterpret_cast<float2*>(sm + RED_OFF + wm * 8192 + rl * 256 + col * 4) = v;
                }
    }
    __syncthreads();
    if (wn == 0) {
#pragma unroll
        for (int mt = 0; mt < 2; ++mt)
#pragma unroll
            for (int nt = 0; nt < 8; ++nt)
#pragma unroll
                for (int rr = 0; rr < 2; ++rr) {
                    int rl = mt * 16 + (lane >> 2) + rr * 8;
                    int col = nt * 8 + ((lane & 3) << 1);
                    float2 p = *reinterpret_cast<float2*>(sm + RED_OFF + wm * 8192 + rl * 256 + col * 4);
                    float2 v = make_float2(po[mt][nt][rr * 2] + p.x,
                                           po[mt][nt][rr * 2 + 1] + p.y);
                    size_t off = (((size_t)b * S_LEN + t0 + mbase + rl) * NH + h) * DIM + col;
                    *reinterpret_cast<float2*>(out + off) = v;
                }
    }
}

extern "C" void kernel_launch(void* const* d_in, const int* in_sizes, int n_in,
                              void* d_out, int out_size) {
    const float* qkv = (const float*)d_in[0];
    float* out = (float*)d_out;
    cudaFuncSetAttribute(ttt_mma_kernel, cudaFuncAttributeMaxDynamicSharedMemorySize,
                         SMEM_TOTAL);
    dim3 grid(32 /*b*h*/, NMB /*reversed T-blocks*/);
    ttt_mma_kernel<<<grid, 128, SMEM_TOTAL>>>(qkv, out);
}

// round 12
// speedup vs baseline: 2.1489x; 1.0136x over previous
#include <cuda_runtime.h>
#include <cuda_bf16.h>
#include <cstdint>

typedef uint32_t u32;

#define S_LEN 2048
#define NH 16
#define DIM 64
#define BLKM 64          // T rows per CTA
#define BLKS 64          // K/V rows per j-step
#define NMB 32           // S_LEN / BLKM
#define ROWSTRIDE 3072   // 3*NH*DIM floats between consecutive s rows

#define HL 8192          // one [64][64] bf16 half-tile (hi or lo)
// smem layout (each buffer = hi tile then lo tile, off64 swizzled)
#define OFF_Q   0        // pass 1: 2Q split tiles; pass 2: fp32 K staging
#define OFF_K   16384
#define OFF_V   32768    // pass 1: fp32 K staging; pass 2: V split tiles
#define OFF_O2  49152
#define SMEM_TOTAL 65536               // -> 3 CTAs/SM
#define RED_OFF OFF_K                  // f32 staging for cross-warp reduce (16KB)

#define NTILE 528                      // sum_{mb} (mb+1)
// A1 tile cache: [bh][tri(mb)+j][4096 floats]. Written pass 1, read pass 2 by
// the SAME thread at the SAME addresses -> no fence needed. ~277 MB, streamed
// with .cs (evict-first) so it does not pollute L2.
__device__ float g_s1[(size_t)32 * NTILE * 4096];

// ------------------------------------------------------------------ helpers
__device__ __forceinline__ u32 smem_u32(const void* p) {
    u32 a; asm("{ .reg .u64 t; cvta.to.shared.u64 t, %1; cvt.u32.u64 %0, t; }"
               : "=r"(a) : "l"(p));
    return a;
}
__device__ __forceinline__ u32 off64(int r, int cb) { return (u32)(r * 128 + (cb ^ ((r & 7) << 4))); }

__device__ __forceinline__ void ldsm4(u32 a, u32& r0, u32& r1, u32& r2, u32& r3) {
    asm volatile("ldmatrix.sync.aligned.m8n8.x4.shared.b16 {%0,%1,%2,%3}, [%4];"
        : "=r"(r0), "=r"(r1), "=r"(r2), "=r"(r3) : "r"(a));
}
__device__ __forceinline__ void ldsm4t(u32 a, u32& r0, u32& r1, u32& r2, u32& r3) {
    asm volatile("ldmatrix.sync.aligned.m8n8.x4.trans.shared.b16 {%0,%1,%2,%3}, [%4];"
        : "=r"(r0), "=r"(r1), "=r"(r2), "=r"(r3) : "r"(a));
}
__device__ __forceinline__ void mma_bf16(float* c, u32 a0, u32 a1, u32 a2, u32 a3,
                                         u32 b0, u32 b1) {
    asm volatile("mma.sync.aligned.m16n8k16.row.col.f32.bf16.bf16.f32 "
        "{%0,%1,%2,%3}, {%4,%5,%6,%7}, {%8,%9}, {%0,%1,%2,%3};"
        : "+f"(c[0]), "+f"(c[1]), "+f"(c[2]), "+f"(c[3])
        : "r"(a0), "r"(a1), "r"(a2), "r"(a3), "r"(b0), "r"(b1));
}
// fast truncation split: hi = top16 (PRMT pack), lo = x - hi (rn bf16x2 pack)
__device__ __forceinline__ void split_pack(float v0, float v1, u32& hp, u32& lp) {
    u32 u0 = __float_as_uint(v0), u1 = __float_as_uint(v1);
    asm("prmt.b32 %0, %1, %2, 0x7632;" : "=r"(hp) : "r"(u0), "r"(u1));
    float lo0 = v0 - __uint_as_float(u0 & 0xFFFF0000u);
    float lo1 = v1 - __uint_as_float(u1 & 0xFFFF0000u);
    asm("cvt.rn.satfinite.bf16x2.f32 %0, %1, %2;" : "=r"(lp) : "f"(lo1), "f"(lo0));
}
// streaming (evict-first) scratch access
__device__ __forceinline__ void stg_cs4(float* p, float a, float b, float c, float d) {
    asm volatile("st.global.cs.v4.f32 [%0], {%1,%2,%3,%4};"
        :: "l"(p), "f"(a), "f"(b), "f"(c), "f"(d) : "memory");
}
__device__ __forceinline__ void ldg_cs4(const float* p, float& a, float& b, float& c, float& d) {
    asm volatile("ld.global.cs.v4.f32 {%0,%1,%2,%3}, [%4];"
        : "=f"(a), "=f"(b), "=f"(c), "=f"(d) : "l"(p));
}

#define CP_COMMIT() asm volatile("cp.async.commit_group;" ::: "memory")
#define CP_WAIT0()  asm volatile("cp.async.wait_group 0;" ::: "memory")

// ---- cp.async: 64x64 fp32 tile -> fp32 stage (128 thr, 8x16B each) ----
__device__ __forceinline__ void cpasync64(u32 stg, const float* src, int tid) {
#pragma unroll
    for (int it = 0; it < 8; ++it) {
        int f = tid + it * 128;
        int s = f >> 4, dq = (f & 15) << 2;
        u32 dst = stg + (u32)(s * 256 + dq * 4);
        const float* g = src + (size_t)s * ROWSTRIDE + dq;
        asm volatile("cp.async.cg.shared.global [%0], [%1], 16;" :: "r"(dst), "l"(g));
    }
    CP_COMMIT();
}
// ---- convert fp32 stage (at stageOff) -> K split-bf16 tiles ----
__device__ __forceinline__ void convert_stage(char* sm, int stageOff, int tid) {
#pragma unroll
    for (int it = 0; it < 8; ++it) {
        int f = tid + it * 128;
        int s = f >> 4, dq = (f & 15) << 2;
        float4 v = *reinterpret_cast<const float4*>(sm + stageOff + s * 256 + dq * 4);
        u32 hp0, lp0, hp1, lp1;
        split_pack(v.x, v.y, hp0, lp0);
        split_pack(v.z, v.w, hp1, lp1);
        u32 o = off64(s, dq << 1);
        *reinterpret_cast<u32*>(sm + OFF_K + o)          = hp0;
        *reinterpret_cast<u32*>(sm + OFF_K + o + 4)      = hp1;
        *reinterpret_cast<u32*>(sm + OFF_K + HL + o)     = lp0;
        *reinterpret_cast<u32*>(sm + OFF_K + HL + o + 4) = lp1;
    }
}

// ---- direct LDG load: 64 x 64 fp32 -> split-bf16 hi/lo swizzled smem (128 thr) ----
__device__ __forceinline__ void load_split(char* sm, int base, const float* src,
                                           float scale, int tid) {
#pragma unroll
    for (int it = 0; it < 8; ++it) {
        int f = tid + it * 128;
        int s = f >> 4, dq = (f & 15) << 2;
        float4 v = *reinterpret_cast<const float4*>(src + (size_t)s * ROWSTRIDE + dq);
        u32 hp0, lp0, hp1, lp1;
        split_pack(v.x * scale, v.y * scale, hp0, lp0);
        split_pack(v.z * scale, v.w * scale, hp1, lp1);
        u32 o = off64(s, dq << 1);
        *reinterpret_cast<u32*>(sm + base + o)          = hp0;
        *reinterpret_cast<u32*>(sm + base + o + 4)      = hp1;
        *reinterpret_cast<u32*>(sm + base + HL + o)     = lp0;
        *reinterpret_cast<u32*>(sm + base + HL + o + 4) = lp1;
    }
}

// ---- GEMM1: acc[32x32 slice] += A[64x64] * (B[64x64])^T, 3-term split ----
__device__ __forceinline__ void gemm_nT(u32 aHi, u32 bHi, float (&acc)[2][4][4],
                                        int lane, int mbase, int nbase) {
    const int arL = lane & 15, acL = (lane >> 4) << 4;
    const int brL = ((lane >> 4) << 3) + (lane & 7), bcL = ((lane >> 3) & 1) << 4;
#pragma unroll
    for (int kk = 0; kk < 4; ++kk) {
        const int kb = kk << 5;
        u32 aH[2][4], aL[2][4];
#pragma unroll
        for (int mt = 0; mt < 2; ++mt) {
            u32 ad = aHi + off64(mbase + mt * 16 + arL, kb + acL);
            ldsm4(ad,      aH[mt][0], aH[mt][1], aH[mt][2], aH[mt][3]);
            ldsm4(ad + HL, aL[mt][0], aL[mt][1], aL[mt][2], aL[mt][3]);
        }
#pragma unroll
        for (int nt2 = 0; nt2 < 2; ++nt2) {
            u32 bd = bHi + off64(nbase + nt2 * 16 + brL, kb + bcL);
            u32 bh0, bh1, bh2, bh3, bl0, bl1, bl2, bl3;
            ldsm4(bd,      bh0, bh1, bh2, bh3);
            ldsm4(bd + HL, bl0, bl1, bl2, bl3);
#pragma unroll
            for (int mt = 0; mt < 2; ++mt) {
                float* c0 = acc[mt][nt2 * 2];
                float* c1 = acc[mt][nt2 * 2 + 1];
                mma_bf16(c0, aH[mt][0], aH[mt][1], aH[mt][2], aH[mt][3], bh0, bh1);
                mma_bf16(c1, aH[mt][0], aH[mt][1], aH[mt][2], aH[mt][3], bh2, bh3);
                mma_bf16(c0, aH[mt][0], aH[mt][1], aH[mt][2], aH[mt][3], bl0, bl1);
                mma_bf16(c1, aH[mt][0], aH[mt][1], aH[mt][2], aH[mt][3], bl2, bl3);
                mma_bf16(c0, aL[mt][0], aL[mt][1], aL[mt][2], aL[mt][3], bh0, bh1);
                mma_bf16(c1, aL[mt][0], aL[mt][1], aL[mt][2], aL[mt][3], bh2, bh3);
            }
        }
    }
}

// ---- mask (absolute row/col) + in-register split into A-operand packs ----
__device__ __forceinline__ void mask_pack(float (&acc)[2][4][4],
                                          u32 (&pH)[2][2][4], u32 (&pL)[2][2][4],
                                          int lane, int rowAbs0, int colAbs0, bool diag) {
    if (diag) {
#pragma unroll
        for (int mt = 0; mt < 2; ++mt)
#pragma unroll
            for (int nt = 0; nt < 4; ++nt) {
                int col = colAbs0 + nt * 8 + ((lane & 3) << 1);
#pragma unroll
                for (int rr = 0; rr < 2; ++rr) {
                    int row = rowAbs0 + mt * 16 + (lane >> 2) + rr * 8;
                    if (col     > row) acc[mt][nt][rr * 2 + 0] = 0.0f;
                    if (col + 1 > row) acc[mt][nt][rr * 2 + 1] = 0.0f;
                }
            }
    }
#pragma unroll
    for (int mt = 0; mt < 2; ++mt)
#pragma unroll
        for (int kk = 0; kk < 2; ++kk) {
            split_pack(acc[mt][2*kk  ][0], acc[mt][2*kk  ][1], pH[mt][kk][0], pL[mt][kk][0]);
            split_pack(acc[mt][2*kk  ][2], acc[mt][2*kk  ][3], pH[mt][kk][1], pL[mt][kk][1]);
            split_pack(acc[mt][2*kk+1][0], acc[mt][2*kk+1][1], pH[mt][kk][2], pL[mt][kk][2]);
            split_pack(acc[mt][2*kk+1][2], acc[mt][2*kk+1][3], pH[mt][kk][3], pL[mt][kk][3]);
        }
}

// ---- GEMM2: po[32x64] += S_slice(regs, 32 k) * B[k-slice x 64], B via ldmatrix.trans ----
__device__ __forceinline__ void gemm2_reg(const u32 (&pH)[2][2][4], const u32 (&pL)[2][2][4],
                                          u32 bHi, float (&po)[2][8][4],
                                          int lane, int kbase) {
    const int brL = (((lane >> 3) & 1) << 3) + (lane & 7), bcL = (lane >> 4) << 4;
#pragma unroll
    for (int kk = 0; kk < 2; ++kk) {
#pragma unroll
        for (int nt2 = 0; nt2 < 4; ++nt2) {
            u32 bd = bHi + off64(kbase + kk * 16 + brL, (nt2 << 5) + bcL);
            u32 bh0, bh1, bh2, bh3, bl0, bl1, bl2, bl3;
            ldsm4t(bd,      bh0, bh1, bh2, bh3);
            ldsm4t(bd + HL, bl0, bl1, bl2, bl3);
#pragma unroll
            for (int mt = 0; mt < 2; ++mt) {
                float* c0 = po[mt][nt2 * 2];
                float* c1 = po[mt][nt2 * 2 + 1];
                mma_bf16(c0, pH[mt][kk][0], pH[mt][kk][1], pH[mt][kk][2], pH[mt][kk][3], bh0, bh1);
                mma_bf16(c1, pH[mt][kk][0], pH[mt][kk][1], pH[mt][kk][2], pH[mt][kk][3], bh2, bh3);
                mma_bf16(c0, pH[mt][kk][0], pH[mt][kk][1], pH[mt][kk][2], pH[mt][kk][3], bl0, bl1);
                mma_bf16(c1, pH[mt][kk][0], pH[mt][kk][1], pH[mt][kk][2], pH[mt][kk][3], bl2, bl3);
                mma_bf16(c0, pL[mt][kk][0], pL[mt][kk][1], pL[mt][kk][2], pL[mt][kk][3], bh0, bh1);
                mma_bf16(c1, pL[mt][kk][0], pL[mt][kk][1], pL[mt][kk][2], pL[mt][kk][3], bh2, bh3);
            }
        }
    }
}

#define ZERO8(po) \
    _Pragma("unroll") for (int mt = 0; mt < 2; ++mt) \
    _Pragma("unroll") for (int nt = 0; nt < 8; ++nt) \
    _Pragma("unroll") for (int e = 0; e < 4; ++e) (po)[mt][nt][e] = 0.0f;
#define ZERO4(a) \
    _Pragma("unroll") for (int mt = 0; mt < 2; ++mt) \
    _Pragma("unroll") for (int nt = 0; nt < 4; ++nt) \
    _Pragma("unroll") for (int e = 0; e < 4; ++e) (a)[mt][nt][e] = 0.0f;

__global__ void __launch_bounds__(128, 3)
ttt_mma_kernel(const float* __restrict__ qkv, float* __restrict__ out) {
    extern __shared__ char sm[];
    const u32 sb = smem_u32(sm);
    const int tid = threadIdx.x, lane = tid & 31, wid = tid >> 5;
    const int wm = wid & 1, wn = wid >> 1;
    const int mbase = wm * 32, nbase = wn * 32;

    const int mb = (NMB - 1) - (int)blockIdx.y;     // heavy T-blocks first
    const int bh = blockIdx.x, b = bh >> 4, h = bh & 15;
    const float* base = qkv + (size_t)b * S_LEN * ROWSTRIDE + h * DIM;
    const float* gQ = base;
    const float* gK = base + NH * DIM;
    const float* gV = base + 2 * NH * DIM;
    const int t0 = mb * BLKM;
    const int nK = mb + 1;                          // 64-row K blocks needed
    const bool diagDead = (wm == 0 && wn == 1);     // fully-masked diag quadrant
    // per-thread scratch base (coalesced: element i of thread t at i*512 + t*4 floats)
    float* scr0 = g_s1 + ((size_t)(bh * NTILE + (mb * (mb + 1)) / 2) << 12) + (tid << 2);

    // kick K0 -> fp32 stage (V buffer, free in pass 1); Q LDG overlaps the copy
    cpasync64(sb + OFF_V, gK, tid);
    load_split(sm, OFF_Q, gQ + (size_t)t0 * ROWSTRIDE, 2.0f, tid);

    // ================= pass 1: po = partial of tril(2Q K^T) K  (= 2*O2) =================
    float po[2][8][4];
    ZERO8(po);
    for (int j = 0; j < nK; ++j) {
        CP_WAIT0(); __syncthreads();                // stage holds K_j; prev gemm2 done with sK
        convert_stage(sm, OFF_V, tid);              // K_j -> split bf16 (LDS, not LDG)
        __syncthreads();                            // sK visible; stage free
        if (j + 1 < nK)
            cpasync64(sb + OFF_V, gK + (size_t)(j + 1) * BLKS * ROWSTRIDE, tid);

        if (!(j == nK - 1 && diagDead)) {
            float acc1[2][4][4];
            ZERO4(acc1);
            gemm_nT(sb + OFF_Q, sb + OFF_K, acc1, lane, mbase, nbase);  // 2Q K^T
            // store raw A1' tile to scratch (pre-mask, evict-first) for pass 2
            {
                float* sp = scr0 + ((size_t)j << 12);
                const float* a = &acc1[0][0][0];
#pragma unroll
                for (int i = 0; i < 8; ++i)
                    stg_cs4(sp + i * 512, a[i*4], a[i*4+1], a[i*4+2], a[i*4+3]);
            }
            u32 pH[2][2][4], pL[2][2][4];
            mask_pack(acc1, pH, pL, lane, t0 + mbase, j * BLKS + nbase, j == nK - 1);
            gemm2_reg(pH, pL, sb + OFF_K, po, lane, nbase);             // += S K
        }
    }

    // cross-warp reduce po (wn pairs) -> -O2 split tiles in sO2
    __syncthreads();
    if (wn == 1) {
#pragma unroll
        for (int mt = 0; mt < 2; ++mt)
#pragma unroll
            for (int nt = 0; nt < 8; ++nt)
#pragma unroll
                for (int rr = 0; rr < 2; ++rr) {
                    int rl = mt * 16 + (lane >> 2) + rr * 8;
                    int col = nt * 8 + ((lane & 3) << 1);
                    float2 v = make_float2(po[mt][nt][rr * 2], po[mt][nt][rr * 2 + 1]);
                    *reinterpret_cast<float2*>(sm + RED_OFF + wm * 8192 + rl * 256 + col * 4) = v;
                }
    }
    __syncthreads();
    if (wn == 0) {
#pragma unroll
        for (int mt = 0; mt < 2; ++mt)
#pragma unroll
            for (int nt = 0; nt < 8; ++nt)
#pragma unroll
                for (int rr = 0; rr < 2; ++rr) {
                    int rl = mt * 16 + (lane >> 2) + rr * 8;
                    int col = nt * 8 + ((lane & 3) << 1);
                    float2 p = *reinterpret_cast<float2*>(sm + RED_OFF + wm * 8192 + rl * 256 + col * 4);
                    float v0 = -0.5f * (po[mt][nt][rr * 2]     + p.x);
                    float v1 = -0.5f * (po[mt][nt][rr * 2 + 1] + p.y);
                    u32 hp, lp;
                    split_pack(v0, v1, hp, lp);
                    u32 o = off64(mbase + rl, col << 1);
                    *reinterpret_cast<u32*>(sm + OFF_O2 + o)      = hp;
                    *reinterpret_cast<u32*>(sm + OFF_O2 + HL + o) = lp;
                }
    }
    // kick K0 -> pass-2 fp32 stage (Q buffer, dead after pass 1)
    cpasync64(sb + OFF_Q, gK, tid);

    // ===== pass 2: po = partial of tril(A1' + (-O2) K^T) V = (2A1 - A2) V =====
    ZERO8(po);
    for (int j = 0; j < nK; ++j) {
        const bool active = !(j == nK - 1 && diagDead);
        float acc1[2][4][4];
        if (active) {                               // reload A1' tile (evict-first;
            float* sp = scr0 + ((size_t)j << 12);   //  latency hides under convert/V load)
            float* a = &acc1[0][0][0];
#pragma unroll
            for (int i = 0; i < 8; ++i)
                ldg_cs4(sp + i * 512, a[i*4], a[i*4+1], a[i*4+2], a[i*4+3]);
        }

        CP_WAIT0(); __syncthreads();                // stage holds K_j; prev gemms done
        convert_stage(sm, OFF_Q, tid);              // K_j -> split bf16 (LDS)
        load_split(sm, OFF_V, gV + (size_t)j * BLKS * ROWSTRIDE, 1.0f, tid);
        __syncthreads();                            // sK, sV visible; stage free
        if (j + 1 < nK)
            cpasync64(sb + OFF_Q, gK + (size_t)(j + 1) * BLKS * ROWSTRIDE, tid);

        if (active) {
            gemm_nT(sb + OFF_O2, sb + OFF_K, acc1, lane, mbase, nbase);  // += (-O2) K^T

            u32 pH[2][2][4], pL[2][2][4];
            mask_pack(acc1, pH, pL, lane, t0 + mbase, j * BLKS + nbase, j == nK - 1);

            gemm2_reg(pH, pL, sb + OFF_V, po, lane, nbase);              // += S V
        }
    }

    // cross-warp reduce po -> final out
    __syncthreads();
    if (wn == 1) {
#pragma unroll
        for (int mt = 0; mt < 2; ++mt)
#pragma unroll
            for (int nt = 0; nt < 8; ++nt)
#pragma unroll
                for (int rr = 0; rr < 2; ++rr) {
                    int rl = mt * 16 + (lane >> 2) + rr * 8;
                    int col = nt * 8 + ((lane & 3) << 1);
                    float2 v = make_float2(po[mt][nt][rr * 2], po[mt][nt][rr * 2 + 1]);
                    *reinterpret_cast<float2*>(sm + RED_OFF + wm * 8192 + rl * 256 + col * 4) = v;
                }
    }
    __syncthreads();
    if (wn == 0) {
#pragma unroll
        for (int mt = 0; mt < 2; ++mt)
#pragma unroll
            for (int nt = 0; nt < 8; ++nt)
#pragma unroll
                for (int rr = 0; rr < 2; ++rr) {
                    int rl = mt * 16 + (lane >> 2) + rr * 8;
                    int col = nt * 8 + ((lane & 3) << 1);
                    float2 p = *reinterpret_cast<float2*>(sm + RED_OFF + wm * 8192 + rl * 256 + col * 4);
                    float2 v = make_float2(po[mt][nt][rr * 2] + p.x,
                                           po[mt][nt][rr * 2 + 1] + p.y);
                    size_t off = (((size_t)b * S_LEN + t0 + mbase + rl) * NH + h) * DIM + col;
                    *reinterpret_cast<float2*>(out + off) = v;
                }
    }
}

extern "C" void kernel_launch(void* const* d_in, const int* in_sizes, int n_in,
                              void* d_out, int out_size) {
    const float* qkv = (const float*)d_in[0];
    float* out = (float*)d_out;
    cudaFuncSetAttribute(ttt_mma_kernel, cudaFuncAttributeMaxDynamicSharedMemorySize,
                         SMEM_TOTAL);
    dim3 grid(32 /*b*h*/, NMB /*reversed T-blocks*/);
    ttt_mma_kernel<<<grid, 128, SMEM_TOTAL>>>(qkv, out);
}